// round 10
// baseline (speedup 1.0000x reference)
#include <cuda_runtime.h>
#include <cstdint>

#define DDIM   128
#define MROWS  131072
#define KHALF  (MROWS/2)

// ---------------- device scratch ----------------
__device__ int      g_rowmap_l[MROWS];
__device__ int      g_rowmap_r[MROWS];
// pass-major pre-swizzled tf32 B fragments (16KB = 4096-word chunks):
//  pass0 {i,u}:    words [0,      65536)  16 chunks (K=16, 2 gate slots of 2048 words)
//  pass1 {fl,fr}:  words [65536, 131072)  16 chunks (K=16, 2 gate slots)
//  pass2 {o}:      words [131072,163840)   8 chunks (K=32, 1 slot of 4096 words)
__device__ uint32_t g_Bpack[163840];

// ---------------- helpers ----------------
__device__ __forceinline__ uint32_t smem_u32(const void* p) {
    uint32_t a;
    asm("{ .reg .u64 t; cvta.to.shared.u64 t, %1; cvt.u32.u64 %0, t; }" : "=r"(a) : "l"(p));
    return a;
}
__device__ __forceinline__ uint32_t f2tf32(float f) {
    uint32_t r; asm("cvt.rna.tf32.f32 %0, %1;" : "=r"(r) : "f"(f)); return r;
}
__device__ __forceinline__ float ex2f(float x) {
    float y; asm("ex2.approx.f32 %0, %1;" : "=f"(y) : "f"(x)); return y;
}
__device__ __forceinline__ float rcpf(float x) {
    float y; asm("rcp.approx.f32 %0, %1;" : "=f"(y) : "f"(x)); return y;
}
__device__ __forceinline__ float sigf(float x) {
    return rcpf(1.0f + ex2f(-1.4426950408889634f * x));
}
__device__ __forceinline__ float tanhf_(float x) {
    return fmaf(2.0f, rcpf(1.0f + ex2f(-2.8853900817779268f * x)), -1.0f);
}
__device__ __forceinline__ void mma_tf32(float* d, const uint32_t* a, const uint32_t* b) {
    asm volatile(
        "mma.sync.aligned.m16n8k8.row.col.f32.tf32.tf32.f32 "
        "{%0,%1,%2,%3}, {%4,%5,%6,%7}, {%8,%9}, {%0,%1,%2,%3};"
        : "+f"(d[0]), "+f"(d[1]), "+f"(d[2]), "+f"(d[3])
        : "r"(a[0]), "r"(a[1]), "r"(a[2]), "r"(a[3]), "r"(b[0]), "r"(b[1]));
}
__device__ __forceinline__ void cpa16(uint32_t dst, const uint32_t* src) {
    asm volatile("cp.async.cg.shared.global [%0], [%1], 16;" :: "r"(dst), "l"(src));
}
__device__ __forceinline__ void cp_commit() {
    asm volatile("cp.async.commit_group;" ::: "memory");
}
__device__ __forceinline__ void pf_l2(const void* p) {
    asm volatile("prefetch.global.L2 [%0];" :: "l"(p));
}

// ---------------- SMEM layout (112 KB exactly -> 2 CTAs/SM) ----------------
#define SMEM_A     0          // 64x256 tf32 fragment-packed = 65536 B
#define SMEM_B     65536      // 3 buffers x 16384 B
#define SMEM_TOTAL 114688

// A pack byte offset (relative to SMEM_A) for element (r,k), r in [0,64)
__device__ __forceinline__ uint32_t a_off(int r, int k) {
    int mt = r >> 4, kk = k >> 3;
    int lane = ((r & 7) << 2) | (k & 3);
    int slot = ((r >> 3) & 1) | (((k >> 2) & 1) << 1);
    return (uint32_t)((((mt << 5) + kk) << 5) + (lane ^ (kk & 7))) * 16u + (uint32_t)slot * 4u;
}

// ---------------- single merged prep kernel ----------------
__global__ void prep_all(const float* __restrict__ W,
                         const int* __restrict__ bf0, const int* __restrict__ bt0,
                         const int* __restrict__ pf0, const int* __restrict__ pt0,
                         const int* __restrict__ bf1, const int* __restrict__ bt1,
                         const int* __restrict__ pf1, const int* __restrict__ pt1) {
    int idx = blockIdx.x * blockDim.x + threadIdx.x;
    if (idx < KHALF) {
        g_rowmap_l[bt0[idx]] = bf0[idx];
        g_rowmap_l[pt0[idx]] = (int)((uint32_t)pf0[idx] | 0x80000000u);
        g_rowmap_r[bt1[idx]] = bf1[idx];
        g_rowmap_r[pt1[idx]] = (int)((uint32_t)pf1[idx] | 0x80000000u);
    }
    if (idx < 256 * 640) {
        int k = idx / 640, col = idx % 640;
        int gate = col >> 7, n = col & 127;     // gates: 0:i 1:o 2:u 3:f_l 4:f_r
        int pass, slot;
        if      (gate == 0) { pass = 0; slot = 0; }
        else if (gate == 2) { pass = 0; slot = 1; }
        else if (gate == 3) { pass = 1; slot = 0; }
        else if (gate == 4) { pass = 1; slot = 1; }
        else                { pass = 2; slot = 0; }
        int nt = n >> 3, nl = n & 7;
        int kl = k & 7;
        int lane = (nl << 2) | (kl & 3);
        int ws = (kl >> 2) & 1;
        int off;
        if (pass < 2) {  // K-chunk 16, 2 slots of 2048 words
            int chunk = k >> 4, kk = (k >> 3) & 1;
            off = pass * 65536 + chunk * 4096 + slot * 2048
                + ((kk * 8 + (nt >> 1)) * 32 + lane) * 4 + (nt & 1) * 2 + ws;
        } else {         // K-chunk 32, 1 slot of 4096 words
            int chunk = k >> 5, kk = (k >> 3) & 3;
            off = 131072 + chunk * 4096
                + ((kk * 8 + (nt >> 1)) * 32 + lane) * 4 + (nt & 1) * 2 + ws;
        }
        g_Bpack[off] = f2tf32(W[idx]);
    }
}

// ---------------- pipelined MMA pass ----------------
// one 16 KB chunk = 4096 words = 1024 x 16B units
__device__ __forceinline__ void issue_chunk16(uint32_t sdst, const uint32_t* src, int tid) {
    #pragma unroll
    for (int i = 0; i < 4; i++) {
        int unit = i * 256 + tid;
        cpa16(sdst + (uint32_t)unit * 16u, src + unit * 4);
    }
    cp_commit();
}

// Stage-3 triple-buffered pass.
// Entry invariant: chunks 0 and 1 of this pass are in flight to buffers
// phase, phase+1 (two cp.async groups pending, oldest = chunk 0).
// Each iter: wait (all but newest group) -> sync -> issue chunk c+2 -> compute c.
// Fill runway for chunk c+2 = compute(c) + compute(c+1) ~ 2 chunk-times.
template<int NS, int NCH, int KS>
__device__ __forceinline__ void run_pass(const uint32_t* __restrict__ gW,
                                         const uint32_t* __restrict__ nextW,
                                         char* smem, uint32_t sbase,
                                         int tid, int wm, int wq, int lane,
                                         float acc[][2][4][4], int& phase) {
    #pragma unroll
    for (int s = 0; s < NS; s++)
        #pragma unroll
        for (int mi = 0; mi < 2; mi++)
            #pragma unroll
            for (int ni = 0; ni < 4; ni++)
                #pragma unroll
                for (int c = 0; c < 4; c++) acc[s][mi][ni][c] = 0.0f;

    int bufc = phase;
    #pragma unroll 1
    for (int c = 0; c < NCH; c++) {
        if (nextW == nullptr && c == NCH - 1)
            asm volatile("cp.async.wait_group 0;" ::: "memory");
        else
            asm volatile("cp.async.wait_group 1;" ::: "memory");   // chunk c landed
        __syncthreads();   // visible to all; compute(c-1) done -> buffer for c+2 free

        int ibuf = bufc + 2; if (ibuf >= 3) ibuf -= 3;
        if (c < NCH - 2)
            issue_chunk16(sbase + SMEM_B + (uint32_t)ibuf * 16384u, gW + (c + 2) * 4096, tid);
        else if (nextW)
            issue_chunk16(sbase + SMEM_B + (uint32_t)ibuf * 16384u, nextW + (c + 2 - NCH) * 4096, tid);

        const char* bb = smem + SMEM_B + bufc * 16384;

        #pragma unroll
        for (int kk = 0; kk < KS; kk++) {
            const int kkg = c * KS + kk;
            uint32_t a[2][4];
            #pragma unroll
            for (int mi = 0; mi < 2; mi++) {
                uint4 v = *(const uint4*)(smem + SMEM_A +
                    (uint32_t)((((wm * 2 + mi) * 32 + kkg) * 32) + (lane ^ (kkg & 7))) * 16u);
                a[mi][0] = v.x; a[mi][1] = v.y; a[mi][2] = v.z; a[mi][3] = v.w;
            }
            uint32_t b[NS][4][2];
            #pragma unroll
            for (int s = 0; s < NS; s++)
                #pragma unroll
                for (int np2 = 0; np2 < 2; np2++) {
                    uint4 v = *(const uint4*)(bb + s * 8192 +
                        (uint32_t)(((kk * 8 + wq * 2 + np2) * 32) + lane) * 16u);
                    b[s][np2 * 2][0]     = v.x; b[s][np2 * 2][1]     = v.y;
                    b[s][np2 * 2 + 1][0] = v.z; b[s][np2 * 2 + 1][1] = v.w;
                }
            #pragma unroll
            for (int s = 0; s < NS; s++)
                #pragma unroll
                for (int mi = 0; mi < 2; mi++)
                    #pragma unroll
                    for (int ni = 0; ni < 4; ni++)
                        mma_tf32(acc[s][mi][ni], a[mi], b[s][ni]);
        }
        bufc++; if (bufc == 3) bufc = 0;
    }
    phase = bufc;
}

// ---------------- main fused kernel ----------------
__global__ void __launch_bounds__(256, 2) treelstm_main(
    const float* __restrict__ h_bot, const float* __restrict__ c_bot,
    const float* __restrict__ h_buf, const float* __restrict__ c_buf,
    const float* __restrict__ bias,  float* __restrict__ out) {
    extern __shared__ char smem[];
    const uint32_t sbase = smem_u32(smem);

    const int tid = threadIdx.x, wid = tid >> 5, lane = tid & 31;
    const int g = lane >> 2, tig = lane & 3;
    const int wm = wid & 1, wq = wid >> 1;
    const int blk = blockIdx.x;
    const int mbase = blk * 64;

    // preload pass0 chunks 0 and 1 (entry invariant: 2 groups in flight)
    issue_chunk16(sbase + SMEM_B,         g_Bpack,        tid);
    issue_chunk16(sbase + SMEM_B + 16384, g_Bpack + 4096, tid);

    // ---- gather X = [h_l | h_r] into fragment-packed A (tf32) ----
    // 64 rows x 2 sources = 128 warp-jobs
    for (int j = wid; j < 128; j += 8) {
        int src = j & 1, r = j >> 1;
        int m = mbase + r;
        int map = src ? g_rowmap_r[m] : g_rowmap_l[m];
        const float* sp = ((map < 0) ? h_buf : h_bot) + (size_t)(uint32_t)(map & 0x7fffffff) * DDIM;
        float4 v = ((const float4*)sp)[lane];
        int k0 = src * 128 + lane * 4;
        char* ab = smem + SMEM_A;
        *(uint32_t*)(ab + a_off(r, k0 + 0)) = f2tf32(v.x);
        *(uint32_t*)(ab + a_off(r, k0 + 1)) = f2tf32(v.y);
        *(uint32_t*)(ab + a_off(r, k0 + 2)) = f2tf32(v.z);
        *(uint32_t*)(ab + a_off(r, k0 + 3)) = f2tf32(v.w);
    }

    float acc[2][2][4][4];
    float creg[2][4][4];
    int phase = 0;

    // ---- pass 0: gates i & u ----
    run_pass<2, 16, 2>(g_Bpack, g_Bpack + 65536, smem, sbase, tid, wm, wq, lane, acc, phase);
    #pragma unroll
    for (int mi = 0; mi < 2; mi++)
        #pragma unroll
        for (int ni = 0; ni < 4; ni++) {
            int colg = wq * 32 + ni * 8 + tig * 2;
            float2 bi = *(const float2*)(bias + colg);         // i: cols 0..127
            float2 bu = *(const float2*)(bias + 256 + colg);   // u: cols 256..383
            creg[mi][ni][0] = sigf(acc[0][mi][ni][0] + bi.x) * tanhf_(acc[1][mi][ni][0] + bu.x);
            creg[mi][ni][1] = sigf(acc[0][mi][ni][1] + bi.y) * tanhf_(acc[1][mi][ni][1] + bu.y);
            creg[mi][ni][2] = sigf(acc[0][mi][ni][2] + bi.x) * tanhf_(acc[1][mi][ni][2] + bu.x);
            creg[mi][ni][3] = sigf(acc[0][mi][ni][3] + bi.y) * tanhf_(acc[1][mi][ni][3] + bu.y);
        }

    // ---- L2-prefetch the c_l/c_r rows this thread will gather after pass 1 ----
    {
        const int colb = wq * 32;
        #pragma unroll
        for (int mi = 0; mi < 2; mi++) {
            int row0 = wm * 32 + mi * 16 + g;
            int ml0 = g_rowmap_l[mbase + row0], ml1 = g_rowmap_l[mbase + row0 + 8];
            int mr0 = g_rowmap_r[mbase + row0], mr1 = g_rowmap_r[mbase + row0 + 8];
            pf_l2(((ml0 < 0) ? c_buf : c_bot) + (size_t)(uint32_t)(ml0 & 0x7fffffff) * DDIM + colb);
            pf_l2(((ml1 < 0) ? c_buf : c_bot) + (size_t)(uint32_t)(ml1 & 0x7fffffff) * DDIM + colb);
            pf_l2(((mr0 < 0) ? c_buf : c_bot) + (size_t)(uint32_t)(mr0 & 0x7fffffff) * DDIM + colb);
            pf_l2(((mr1 < 0) ? c_buf : c_bot) + (size_t)(uint32_t)(mr1 & 0x7fffffff) * DDIM + colb);
        }
    }

    // ---- pass 1: f_l & f_r together ----
    run_pass<2, 16, 2>(g_Bpack + 65536, g_Bpack + 131072, smem, sbase, tid, wm, wq, lane, acc, phase);
    #pragma unroll
    for (int mi = 0; mi < 2; mi++) {
        int row0 = wm * 32 + mi * 16 + g;
        int ml0 = g_rowmap_l[mbase + row0], ml1 = g_rowmap_l[mbase + row0 + 8];
        int mr0 = g_rowmap_r[mbase + row0], mr1 = g_rowmap_r[mbase + row0 + 8];
        const float* cl0 = ((ml0 < 0) ? c_buf : c_bot) + (size_t)(uint32_t)(ml0 & 0x7fffffff) * DDIM;
        const float* cl1 = ((ml1 < 0) ? c_buf : c_bot) + (size_t)(uint32_t)(ml1 & 0x7fffffff) * DDIM;
        const float* cr0 = ((mr0 < 0) ? c_buf : c_bot) + (size_t)(uint32_t)(mr0 & 0x7fffffff) * DDIM;
        const float* cr1 = ((mr1 < 0) ? c_buf : c_bot) + (size_t)(uint32_t)(mr1 & 0x7fffffff) * DDIM;
        #pragma unroll
        for (int ni = 0; ni < 4; ni++) {
            int colg = wq * 32 + ni * 8 + tig * 2;
            float2 bl = *(const float2*)(bias + 384 + colg);   // f_l
            float2 br = *(const float2*)(bias + 512 + colg);   // f_r
            float2 vl0 = *(const float2*)(cl0 + colg);
            float2 vl1 = *(const float2*)(cl1 + colg);
            float2 vr0 = *(const float2*)(cr0 + colg);
            float2 vr1 = *(const float2*)(cr1 + colg);
            creg[mi][ni][0] = fmaf(sigf(acc[0][mi][ni][0] + bl.x), vl0.x, creg[mi][ni][0]);
            creg[mi][ni][1] = fmaf(sigf(acc[0][mi][ni][1] + bl.y), vl0.y, creg[mi][ni][1]);
            creg[mi][ni][2] = fmaf(sigf(acc[0][mi][ni][2] + bl.x), vl1.x, creg[mi][ni][2]);
            creg[mi][ni][3] = fmaf(sigf(acc[0][mi][ni][3] + bl.y), vl1.y, creg[mi][ni][3]);
            creg[mi][ni][0] = fmaf(sigf(acc[1][mi][ni][0] + br.x), vr0.x, creg[mi][ni][0]);
            creg[mi][ni][1] = fmaf(sigf(acc[1][mi][ni][1] + br.y), vr0.y, creg[mi][ni][1]);
            creg[mi][ni][2] = fmaf(sigf(acc[1][mi][ni][2] + br.x), vr1.x, creg[mi][ni][2]);
            creg[mi][ni][3] = fmaf(sigf(acc[1][mi][ni][3] + br.y), vr1.y, creg[mi][ni][3]);
        }
    }

    // ---- pass 2: o -> finalize h, c ----
    run_pass<1, 8, 4>(g_Bpack + 131072, nullptr, smem, sbase, tid, wm, wq, lane, acc, phase);
    #pragma unroll
    for (int mi = 0; mi < 2; mi++) {
        int row0 = wm * 32 + mi * 16 + g;
        size_t m0 = (size_t)(mbase + row0);
        size_t m1 = m0 + 8;
        #pragma unroll
        for (int ni = 0; ni < 4; ni++) {
            int colg = wq * 32 + ni * 8 + tig * 2;
            float2 bo = *(const float2*)(bias + 128 + colg);   // o: cols 128..255
            float2 h0, h1, c0, c1;
            c0.x = creg[mi][ni][0]; h0.x = sigf(acc[0][mi][ni][0] + bo.x) * tanhf_(c0.x);
            c0.y = creg[mi][ni][1]; h0.y = sigf(acc[0][mi][ni][1] + bo.y) * tanhf_(c0.y);
            c1.x = creg[mi][ni][2]; h1.x = sigf(acc[0][mi][ni][2] + bo.x) * tanhf_(c1.x);
            c1.y = creg[mi][ni][3]; h1.y = sigf(acc[0][mi][ni][3] + bo.y) * tanhf_(c1.y);
            *(float2*)(out + m0 * DDIM + colg) = h0;
            *(float2*)(out + m1 * DDIM + colg) = h1;
            *(float2*)(out + (size_t)MROWS * DDIM + m0 * DDIM + colg) = c0;
            *(float2*)(out + (size_t)MROWS * DDIM + m1 * DDIM + colg) = c1;
        }
    }
}

// ---------------- launch ----------------
extern "C" void kernel_launch(void* const* d_in, const int* in_sizes, int n_in,
                              void* d_out, int out_size) {
    const float* h_bot = (const float*)d_in[0];
    const float* c_bot = (const float*)d_in[1];
    const float* h_buf = (const float*)d_in[2];
    const float* c_buf = (const float*)d_in[3];
    const float* W     = (const float*)d_in[4];
    const float* b     = (const float*)d_in[5];
    const int* bf0 = (const int*)d_in[6];
    const int* bt0 = (const int*)d_in[7];
    const int* pf0 = (const int*)d_in[8];
    const int* pt0 = (const int*)d_in[9];
    const int* bf1 = (const int*)d_in[10];
    const int* bt1 = (const int*)d_in[11];
    const int* pf1 = (const int*)d_in[12];
    const int* pt1 = (const int*)d_in[13];
    float* out = (float*)d_out;

    cudaFuncSetAttribute(treelstm_main, cudaFuncAttributeMaxDynamicSharedMemorySize, SMEM_TOTAL);

    prep_all<<<640, 256>>>(W, bf0, bt0, pf0, pt0, bf1, bt1, pf1, pt1);
    treelstm_main<<<MROWS / 64, 256, SMEM_TOTAL>>>(h_bot, c_bot, h_buf, c_buf, b, out);
}

// round 11
// speedup vs baseline: 1.6537x; 1.6537x over previous
#include <cuda_runtime.h>
#include <cstdint>

#define DDIM   128
#define MROWS  131072
#define KHALF  (MROWS/2)

// ---------------- device scratch ----------------
__device__ int      g_rowmap_l[MROWS];
__device__ int      g_rowmap_r[MROWS];
// pass-major pre-swizzled tf32 B fragments, warp-sliced:
//  chunk = 4096 words (16KB); within chunk: 8 slices of 512 words (one per warp wq)
//  slice: 4 lines x 128 words; line = slot*KS + kk; within line: lane*4 + ntl*2 + ws
//  pass0 {i,u}:    words [0,      65536)  16 chunks (K=16, NS=2, KS=2)
//  pass1 {fl,fr}:  words [65536, 131072)  16 chunks (K=16, NS=2, KS=2)
//  pass2 {o}:      words [131072,163840)   8 chunks (K=32, NS=1, KS=4)
__device__ uint32_t g_Bpack[163840];

// ---------------- helpers ----------------
__device__ __forceinline__ uint32_t smem_u32(const void* p) {
    uint32_t a;
    asm("{ .reg .u64 t; cvta.to.shared.u64 t, %1; cvt.u32.u64 %0, t; }" : "=r"(a) : "l"(p));
    return a;
}
__device__ __forceinline__ uint32_t f2tf32(float f) {
    uint32_t r; asm("cvt.rna.tf32.f32 %0, %1;" : "=r"(r) : "f"(f)); return r;
}
__device__ __forceinline__ float ex2f(float x) {
    float y; asm("ex2.approx.f32 %0, %1;" : "=f"(y) : "f"(x)); return y;
}
__device__ __forceinline__ float rcpf(float x) {
    float y; asm("rcp.approx.f32 %0, %1;" : "=f"(y) : "f"(x)); return y;
}
__device__ __forceinline__ float sigf(float x) {
    return rcpf(1.0f + ex2f(-1.4426950408889634f * x));
}
__device__ __forceinline__ float tanhf_(float x) {
    return fmaf(2.0f, rcpf(1.0f + ex2f(-2.8853900817779268f * x)), -1.0f);
}
__device__ __forceinline__ void mma_tf32(float* d, const uint32_t* a, const uint32_t* b) {
    asm volatile(
        "mma.sync.aligned.m16n8k8.row.col.f32.tf32.tf32.f32 "
        "{%0,%1,%2,%3}, {%4,%5,%6,%7}, {%8,%9}, {%0,%1,%2,%3};"
        : "+f"(d[0]), "+f"(d[1]), "+f"(d[2]), "+f"(d[3])
        : "r"(a[0]), "r"(a[1]), "r"(a[2]), "r"(a[3]), "r"(b[0]), "r"(b[1]));
}
__device__ __forceinline__ void cpa16(uint32_t dst, const uint32_t* src) {
    asm volatile("cp.async.cg.shared.global [%0], [%1], 16;" :: "r"(dst), "l"(src));
}
__device__ __forceinline__ void cp_commit() {
    asm volatile("cp.async.commit_group;" ::: "memory");
}
__device__ __forceinline__ void pf_l2(const void* p) {
    asm volatile("prefetch.global.L2 [%0];" :: "l"(p));
}

// ---------------- SMEM layout (114688 B exactly -> 2 CTAs/SM) ----------------
#define SMEM_A     0          // 64x256 tf32 fragment-packed = 65536 B
#define SMEM_B     65536      // 8 warps x 3 bufs x 2048 B = 49152 B
#define SMEM_TOTAL 114688

// A pack byte offset (relative to SMEM_A) for element (r,k), r in [0,64)
__device__ __forceinline__ uint32_t a_off(int r, int k) {
    int mt = r >> 4, kk = k >> 3;
    int lane = ((r & 7) << 2) | (k & 3);
    int slot = ((r >> 3) & 1) | (((k >> 2) & 1) << 1);
    return (uint32_t)((((mt << 5) + kk) << 5) + (lane ^ (kk & 7))) * 16u + (uint32_t)slot * 4u;
}

// ---------------- single merged prep kernel ----------------
__global__ void prep_all(const float* __restrict__ W,
                         const int* __restrict__ bf0, const int* __restrict__ bt0,
                         const int* __restrict__ pf0, const int* __restrict__ pt0,
                         const int* __restrict__ bf1, const int* __restrict__ bt1,
                         const int* __restrict__ pf1, const int* __restrict__ pt1) {
    int idx = blockIdx.x * blockDim.x + threadIdx.x;
    if (idx < KHALF) {
        g_rowmap_l[bt0[idx]] = bf0[idx];
        g_rowmap_l[pt0[idx]] = (int)((uint32_t)pf0[idx] | 0x80000000u);
        g_rowmap_r[bt1[idx]] = bf1[idx];
        g_rowmap_r[pt1[idx]] = (int)((uint32_t)pf1[idx] | 0x80000000u);
    }
    if (idx < 256 * 640) {
        int k = idx / 640, col = idx % 640;
        int gate = col >> 7, n = col & 127;     // gates: 0:i 1:o 2:u 3:f_l 4:f_r
        int pass, slot;
        if      (gate == 0) { pass = 0; slot = 0; }
        else if (gate == 2) { pass = 0; slot = 1; }
        else if (gate == 3) { pass = 1; slot = 0; }
        else if (gate == 4) { pass = 1; slot = 1; }
        else                { pass = 2; slot = 0; }
        int nt = n >> 3;               // 0..15
        int p  = nt >> 1;              // warp slice 0..7
        int ntl = nt & 1;
        int nl = n & 7;
        int kl = k & 7;
        int lane = (nl << 2) | (kl & 3);
        int ws = (kl >> 2) & 1;
        int off;
        if (pass < 2) {  // K-chunk 16: chunk = k>>4, kk = (k>>3)&1, KS=2
            int chunk = k >> 4, kk = (k >> 3) & 1;
            off = pass * 65536 + chunk * 4096 + p * 512
                + (slot * 2 + kk) * 128 + lane * 4 + ntl * 2 + ws;
        } else {         // K-chunk 32: chunk = k>>5, kk = (k>>3)&3, KS=4
            int chunk = k >> 5, kk = (k >> 3) & 3;
            off = 131072 + chunk * 4096 + p * 512
                + kk * 128 + lane * 4 + ntl * 2 + ws;
        }
        g_Bpack[off] = f2tf32(W[idx]);
    }
}

// ---------------- warp-private slice fill ----------------
// one slice = 512 words = 2048 B = 128 uint4 = 4 per lane
__device__ __forceinline__ void issue_slice(uint32_t sdst, const uint32_t* src, int lane) {
    #pragma unroll
    for (int i = 0; i < 4; i++) {
        int unit = i * 32 + lane;
        cpa16(sdst + (uint32_t)unit * 16u, src + unit * 4);
    }
    cp_commit();
}

// ---------------- barrier-free warp-private pass ----------------
// Entry invariant (per warp): slices for chunks 0,1 of this pass are in flight
// to buffers phase, phase+1 (two cp.async groups pending, oldest = chunk 0).
// No __syncthreads anywhere: buffers are warp-private; reuse is safe by
// program order within the warp.
template<int NS, int NCH, int KS>
__device__ __forceinline__ void run_pass(const uint32_t* __restrict__ gW,
                                         const uint32_t* __restrict__ nextW,
                                         const char* smem, uint32_t warpB_s,
                                         const char* warpB_c, int lane, int wq,
                                         float acc[][4][2][4], int& phase) {
    #pragma unroll
    for (int s = 0; s < NS; s++)
        #pragma unroll
        for (int mt = 0; mt < 4; mt++)
            #pragma unroll
            for (int ntl = 0; ntl < 2; ntl++)
                #pragma unroll
                for (int j = 0; j < 4; j++) acc[s][mt][ntl][j] = 0.0f;

    int bufc = phase;
    #pragma unroll 1
    for (int c = 0; c < NCH; c++) {
        if (nextW == nullptr && c == NCH - 1)
            asm volatile("cp.async.wait_group 0;" ::: "memory");
        else
            asm volatile("cp.async.wait_group 1;" ::: "memory");   // chunk c landed

        int ibuf = bufc + 2; if (ibuf >= 3) ibuf -= 3;
        if (c < NCH - 2)
            issue_slice(warpB_s + (uint32_t)ibuf * 2048u, gW + (c + 2) * 4096 + wq * 512, lane);
        else if (nextW)
            issue_slice(warpB_s + (uint32_t)ibuf * 2048u, nextW + (c + 2 - NCH) * 4096 + wq * 512, lane);

        const char* bb = warpB_c + bufc * 2048;

        #pragma unroll
        for (int kk = 0; kk < KS; kk++) {
            const int kkg = c * KS + kk;
            uint32_t a[4][4];
            #pragma unroll
            for (int mt = 0; mt < 4; mt++) {
                uint4 v = *(const uint4*)(smem + SMEM_A +
                    (uint32_t)(((mt * 32 + kkg) * 32) + (lane ^ (kkg & 7))) * 16u);
                a[mt][0] = v.x; a[mt][1] = v.y; a[mt][2] = v.z; a[mt][3] = v.w;
            }
            #pragma unroll
            for (int s = 0; s < NS; s++) {
                uint4 bv = *(const uint4*)(bb + (s * KS + kk) * 512 + lane * 16);
                uint32_t b0[2] = {bv.x, bv.y};
                uint32_t b1[2] = {bv.z, bv.w};
                #pragma unroll
                for (int mt = 0; mt < 4; mt++) {
                    mma_tf32(acc[s][mt][0], a[mt], b0);
                    mma_tf32(acc[s][mt][1], a[mt], b1);
                }
            }
        }
        bufc++; if (bufc == 3) bufc = 0;
    }
    phase = bufc;
}

// ---------------- main fused kernel ----------------
__global__ void __launch_bounds__(256, 2) treelstm_main(
    const float* __restrict__ h_bot, const float* __restrict__ c_bot,
    const float* __restrict__ h_buf, const float* __restrict__ c_buf,
    const float* __restrict__ bias,  float* __restrict__ out) {
    extern __shared__ char smem[];
    const uint32_t sbase = smem_u32(smem);

    const int tid = threadIdx.x, wid = tid >> 5, lane = tid & 31;
    const int g = lane >> 2, tig = lane & 3;
    const int wq = wid;                          // warp owns N-cols [wq*16, wq*16+16)
    const int blk = blockIdx.x;
    const int mbase = blk * 64;

    const uint32_t warpB_s = sbase + SMEM_B + (uint32_t)wid * 6144u;
    const char*    warpB_c = smem + SMEM_B + wid * 6144;

    // preload this warp's slices for pass0 chunks 0,1 (entry invariant)
    issue_slice(warpB_s,         g_Bpack + wq * 512,        lane);
    issue_slice(warpB_s + 2048u, g_Bpack + 4096 + wq * 512, lane);

    // ---- gather X = [h_l | h_r] into fragment-packed A (tf32) ----
    // 64 rows x 2 sources = 128 warp-jobs
    for (int j = wid; j < 128; j += 8) {
        int src = j & 1, r = j >> 1;
        int m = mbase + r;
        int map = src ? g_rowmap_r[m] : g_rowmap_l[m];
        const float* sp = ((map < 0) ? h_buf : h_bot) + (size_t)(uint32_t)(map & 0x7fffffff) * DDIM;
        float4 v = ((const float4*)sp)[lane];
        int k0 = src * 128 + lane * 4;
        char* ab = smem + SMEM_A;
        *(uint32_t*)(ab + a_off(r, k0 + 0)) = f2tf32(v.x);
        *(uint32_t*)(ab + a_off(r, k0 + 1)) = f2tf32(v.y);
        *(uint32_t*)(ab + a_off(r, k0 + 2)) = f2tf32(v.z);
        *(uint32_t*)(ab + a_off(r, k0 + 3)) = f2tf32(v.w);
    }
    __syncthreads();   // the ONLY CTA barrier: A tile visible to all warps

    float acc[2][4][2][4];   // [slot][mt][ntl][frag]
    float creg[4][2][4];
    int phase = 0;

    // ---- pass 0: gates i & u ----
    run_pass<2, 16, 2>(g_Bpack, g_Bpack + 65536, smem, warpB_s, warpB_c, lane, wq, acc, phase);
    #pragma unroll
    for (int mt = 0; mt < 4; mt++)
        #pragma unroll
        for (int ntl = 0; ntl < 2; ntl++) {
            int colg = wq * 16 + ntl * 8 + tig * 2;
            float2 bi = *(const float2*)(bias + colg);         // i: cols 0..127
            float2 bu = *(const float2*)(bias + 256 + colg);   // u: cols 256..383
            creg[mt][ntl][0] = sigf(acc[0][mt][ntl][0] + bi.x) * tanhf_(acc[1][mt][ntl][0] + bu.x);
            creg[mt][ntl][1] = sigf(acc[0][mt][ntl][1] + bi.y) * tanhf_(acc[1][mt][ntl][1] + bu.y);
            creg[mt][ntl][2] = sigf(acc[0][mt][ntl][2] + bi.x) * tanhf_(acc[1][mt][ntl][2] + bu.x);
            creg[mt][ntl][3] = sigf(acc[0][mt][ntl][3] + bi.y) * tanhf_(acc[1][mt][ntl][3] + bu.y);
        }

    // ---- L2-prefetch the c_l/c_r rows this thread gathers after pass 1 ----
    {
        const int colb = wq * 16;
        #pragma unroll
        for (int mt = 0; mt < 4; mt++) {
            int r0 = mt * 16 + g;
            int ml0 = g_rowmap_l[mbase + r0], ml1 = g_rowmap_l[mbase + r0 + 8];
            int mr0 = g_rowmap_r[mbase + r0], mr1 = g_rowmap_r[mbase + r0 + 8];
            pf_l2(((ml0 < 0) ? c_buf : c_bot) + (size_t)(uint32_t)(ml0 & 0x7fffffff) * DDIM + colb);
            pf_l2(((ml1 < 0) ? c_buf : c_bot) + (size_t)(uint32_t)(ml1 & 0x7fffffff) * DDIM + colb);
            pf_l2(((mr0 < 0) ? c_buf : c_bot) + (size_t)(uint32_t)(mr0 & 0x7fffffff) * DDIM + colb);
            pf_l2(((mr1 < 0) ? c_buf : c_bot) + (size_t)(uint32_t)(mr1 & 0x7fffffff) * DDIM + colb);
        }
    }

    // ---- pass 1: f_l & f_r together ----
    run_pass<2, 16, 2>(g_Bpack + 65536, g_Bpack + 131072, smem, warpB_s, warpB_c, lane, wq, acc, phase);
    #pragma unroll
    for (int mt = 0; mt < 4; mt++) {
        int r0 = mt * 16 + g;
        int ml0 = g_rowmap_l[mbase + r0], ml1 = g_rowmap_l[mbase + r0 + 8];
        int mr0 = g_rowmap_r[mbase + r0], mr1 = g_rowmap_r[mbase + r0 + 8];
        const float* cl0 = ((ml0 < 0) ? c_buf : c_bot) + (size_t)(uint32_t)(ml0 & 0x7fffffff) * DDIM;
        const float* cl1 = ((ml1 < 0) ? c_buf : c_bot) + (size_t)(uint32_t)(ml1 & 0x7fffffff) * DDIM;
        const float* cr0 = ((mr0 < 0) ? c_buf : c_bot) + (size_t)(uint32_t)(mr0 & 0x7fffffff) * DDIM;
        const float* cr1 = ((mr1 < 0) ? c_buf : c_bot) + (size_t)(uint32_t)(mr1 & 0x7fffffff) * DDIM;
        #pragma unroll
        for (int ntl = 0; ntl < 2; ntl++) {
            int colg = wq * 16 + ntl * 8 + tig * 2;
            float2 bl = *(const float2*)(bias + 384 + colg);   // f_l
            float2 br = *(const float2*)(bias + 512 + colg);   // f_r
            float2 vl0 = *(const float2*)(cl0 + colg);
            float2 vl1 = *(const float2*)(cl1 + colg);
            float2 vr0 = *(const float2*)(cr0 + colg);
            float2 vr1 = *(const float2*)(cr1 + colg);
            creg[mt][ntl][0] = fmaf(sigf(acc[0][mt][ntl][0] + bl.x), vl0.x, creg[mt][ntl][0]);
            creg[mt][ntl][1] = fmaf(sigf(acc[0][mt][ntl][1] + bl.y), vl0.y, creg[mt][ntl][1]);
            creg[mt][ntl][2] = fmaf(sigf(acc[0][mt][ntl][2] + bl.x), vl1.x, creg[mt][ntl][2]);
            creg[mt][ntl][3] = fmaf(sigf(acc[0][mt][ntl][3] + bl.y), vl1.y, creg[mt][ntl][3]);
            creg[mt][ntl][0] = fmaf(sigf(acc[1][mt][ntl][0] + br.x), vr0.x, creg[mt][ntl][0]);
            creg[mt][ntl][1] = fmaf(sigf(acc[1][mt][ntl][1] + br.y), vr0.y, creg[mt][ntl][1]);
            creg[mt][ntl][2] = fmaf(sigf(acc[1][mt][ntl][2] + br.x), vr1.x, creg[mt][ntl][2]);
            creg[mt][ntl][3] = fmaf(sigf(acc[1][mt][ntl][3] + br.y), vr1.y, creg[mt][ntl][3]);
        }
    }

    // ---- pass 2: o -> finalize h, c ----
    run_pass<1, 8, 4>(g_Bpack + 131072, nullptr, smem, warpB_s, warpB_c, lane, wq, acc, phase);
    #pragma unroll
    for (int mt = 0; mt < 4; mt++) {
        size_t m0 = (size_t)(mbase + mt * 16 + g);
        size_t m1 = m0 + 8;
        #pragma unroll
        for (int ntl = 0; ntl < 2; ntl++) {
            int colg = wq * 16 + ntl * 8 + tig * 2;
            float2 bo = *(const float2*)(bias + 128 + colg);   // o: cols 128..255
            float2 h0, h1, c0, c1;
            c0.x = creg[mt][ntl][0]; h0.x = sigf(acc[0][mt][ntl][0] + bo.x) * tanhf_(c0.x);
            c0.y = creg[mt][ntl][1]; h0.y = sigf(acc[0][mt][ntl][1] + bo.y) * tanhf_(c0.y);
            c1.x = creg[mt][ntl][2]; h1.x = sigf(acc[0][mt][ntl][2] + bo.x) * tanhf_(c1.x);
            c1.y = creg[mt][ntl][3]; h1.y = sigf(acc[0][mt][ntl][3] + bo.y) * tanhf_(c1.y);
            *(float2*)(out + m0 * DDIM + colg) = h0;
            *(float2*)(out + m1 * DDIM + colg) = h1;
            *(float2*)(out + (size_t)MROWS * DDIM + m0 * DDIM + colg) = c0;
            *(float2*)(out + (size_t)MROWS * DDIM + m1 * DDIM + colg) = c1;
        }
    }
}

// ---------------- launch ----------------
extern "C" void kernel_launch(void* const* d_in, const int* in_sizes, int n_in,
                              void* d_out, int out_size) {
    const float* h_bot = (const float*)d_in[0];
    const float* c_bot = (const float*)d_in[1];
    const float* h_buf = (const float*)d_in[2];
    const float* c_buf = (const float*)d_in[3];
    const float* W     = (const float*)d_in[4];
    const float* b     = (const float*)d_in[5];
    const int* bf0 = (const int*)d_in[6];
    const int* bt0 = (const int*)d_in[7];
    const int* pf0 = (const int*)d_in[8];
    const int* pt0 = (const int*)d_in[9];
    const int* bf1 = (const int*)d_in[10];
    const int* bt1 = (const int*)d_in[11];
    const int* pf1 = (const int*)d_in[12];
    const int* pt1 = (const int*)d_in[13];
    float* out = (float*)d_out;

    cudaFuncSetAttribute(treelstm_main, cudaFuncAttributeMaxDynamicSharedMemorySize, SMEM_TOTAL);

    prep_all<<<640, 256>>>(W, bf0, bt0, pf0, pt0, bf1, bt1, pf1, pt1);
    treelstm_main<<<MROWS / 64, 256, SMEM_TOTAL>>>(h_bot, c_bot, h_buf, c_buf, b, out);
}

// round 13
// speedup vs baseline: 1.6888x; 1.0213x over previous
#include <cuda_runtime.h>
#include <cstdint>

#define DDIM   128
#define MROWS  131072
#define KHALF  (MROWS/2)

// ---------------- device scratch ----------------
__device__ int      g_rowmap_l[MROWS];
__device__ int      g_rowmap_r[MROWS];
// pass-major pre-swizzled tf32 B fragments, warp-sliced:
//  chunk = 4096 words (16KB); within chunk: 8 slices of 512 words (one per warp wq)
//  slice: 4 lines x 128 words; line = slot*KS + kk; within line: lane*4 + ntl*2 + ws
//  pass0 {i,u}:    words [0,      65536)  16 chunks (K=16, NS=2, KS=2)
//  pass1 {fl,fr}:  words [65536, 131072)  16 chunks (K=16, NS=2, KS=2)
//  pass2 {o}:      words [131072,163840)   8 chunks (K=32, NS=1, KS=4)
__device__ uint32_t g_Bpack[163840];

// ---------------- helpers ----------------
__device__ __forceinline__ uint32_t smem_u32(const void* p) {
    uint32_t a;
    asm("{ .reg .u64 t; cvta.to.shared.u64 t, %1; cvt.u32.u64 %0, t; }" : "=r"(a) : "l"(p));
    return a;
}
__device__ __forceinline__ uint32_t f2tf32(float f) {
    uint32_t r; asm("cvt.rna.tf32.f32 %0, %1;" : "=r"(r) : "f"(f)); return r;
}
__device__ __forceinline__ float ex2f(float x) {
    float y; asm("ex2.approx.f32 %0, %1;" : "=f"(y) : "f"(x)); return y;
}
__device__ __forceinline__ float rcpf(float x) {
    float y; asm("rcp.approx.f32 %0, %1;" : "=f"(y) : "f"(x)); return y;
}
__device__ __forceinline__ float sigf(float x) {
    return rcpf(1.0f + ex2f(-1.4426950408889634f * x));
}
__device__ __forceinline__ float tanhf_(float x) {
    return fmaf(2.0f, rcpf(1.0f + ex2f(-2.8853900817779268f * x)), -1.0f);
}
__device__ __forceinline__ void mma_tf32(float* d, const uint32_t* a, const uint32_t* b) {
    asm volatile(
        "mma.sync.aligned.m16n8k8.row.col.f32.tf32.tf32.f32 "
        "{%0,%1,%2,%3}, {%4,%5,%6,%7}, {%8,%9}, {%0,%1,%2,%3};"
        : "+f"(d[0]), "+f"(d[1]), "+f"(d[2]), "+f"(d[3])
        : "r"(a[0]), "r"(a[1]), "r"(a[2]), "r"(a[3]), "r"(b[0]), "r"(b[1]));
}
__device__ __forceinline__ void cpa16(uint32_t dst, const uint32_t* src) {
    asm volatile("cp.async.cg.shared.global [%0], [%1], 16;" :: "r"(dst), "l"(src));
}
__device__ __forceinline__ void cp_commit() {
    asm volatile("cp.async.commit_group;" ::: "memory");
}
__device__ __forceinline__ void pf_l2(const void* p) {
    asm volatile("prefetch.global.L2 [%0];" :: "l"(p));
}

// ---------------- SMEM layout (114688 B exactly -> 2 CTAs/SM) ----------------
#define SMEM_A     0          // 64x256 tf32 fragment-packed = 65536 B
#define SMEM_B     65536      // 8 warps x 3 bufs x 2048 B = 49152 B
#define SMEM_TOTAL 114688

// A pack byte offset (relative to SMEM_A) for element (r,k), r in [0,64)
__device__ __forceinline__ uint32_t a_off(int r, int k) {
    int mt = r >> 4, kk = k >> 3;
    int lane = ((r & 7) << 2) | (k & 3);
    int slot = ((r >> 3) & 1) | (((k >> 2) & 1) << 1);
    return (uint32_t)((((mt << 5) + kk) << 5) + (lane ^ (kk & 7))) * 16u + (uint32_t)slot * 4u;
}

// ---------------- single merged prep kernel ----------------
__global__ void prep_all(const float* __restrict__ W,
                         const int* __restrict__ bf0, const int* __restrict__ bt0,
                         const int* __restrict__ pf0, const int* __restrict__ pt0,
                         const int* __restrict__ bf1, const int* __restrict__ bt1,
                         const int* __restrict__ pf1, const int* __restrict__ pt1) {
    int idx = blockIdx.x * blockDim.x + threadIdx.x;
    if (idx < KHALF) {
        g_rowmap_l[bt0[idx]] = bf0[idx];
        g_rowmap_l[pt0[idx]] = (int)((uint32_t)pf0[idx] | 0x80000000u);
        g_rowmap_r[bt1[idx]] = bf1[idx];
        g_rowmap_r[pt1[idx]] = (int)((uint32_t)pf1[idx] | 0x80000000u);
    }
    if (idx < 256 * 640) {
        int k = idx / 640, col = idx % 640;
        int gate = col >> 7, n = col & 127;     // gates: 0:i 1:o 2:u 3:f_l 4:f_r
        int pass, slot;
        if      (gate == 0) { pass = 0; slot = 0; }
        else if (gate == 2) { pass = 0; slot = 1; }
        else if (gate == 3) { pass = 1; slot = 0; }
        else if (gate == 4) { pass = 1; slot = 1; }
        else                { pass = 2; slot = 0; }
        int nt = n >> 3;               // 0..15
        int p  = nt >> 1;              // warp slice 0..7
        int ntl = nt & 1;
        int nl = n & 7;
        int kl = k & 7;
        int lane = (nl << 2) | (kl & 3);
        int ws = (kl >> 2) & 1;
        int off;
        if (pass < 2) {  // K-chunk 16: chunk = k>>4, kk = (k>>3)&1, KS=2
            int chunk = k >> 4, kk = (k >> 3) & 1;
            off = pass * 65536 + chunk * 4096 + p * 512
                + (slot * 2 + kk) * 128 + lane * 4 + ntl * 2 + ws;
        } else {         // K-chunk 32: chunk = k>>5, kk = (k>>3)&3, KS=4
            int chunk = k >> 5, kk = (k >> 3) & 3;
            off = 131072 + chunk * 4096 + p * 512
                + kk * 128 + lane * 4 + ntl * 2 + ws;
        }
        g_Bpack[off] = f2tf32(W[idx]);
    }
}

// ---------------- warp-private slice fill ----------------
// one slice = 512 words = 2048 B = 128 uint4 = 4 per lane
__device__ __forceinline__ void issue_slice(uint32_t sdst, const uint32_t* src, int lane) {
    #pragma unroll
    for (int i = 0; i < 4; i++) {
        int unit = i * 32 + lane;
        cpa16(sdst + (uint32_t)unit * 16u, src + unit * 4);
    }
    cp_commit();
}

// ---------------- barrier-free warp-private pass ----------------
// Entry invariant (per warp): slices for chunks 0,1 of this pass are in flight
// to buffers phase, phase+1 (two cp.async groups pending, oldest = chunk 0).
// Each iter: ISSUE chunk c+2 (into buffer holding consumed chunk c-1), THEN
// wait for chunk c, then compute. Pending after issue = 3 -> wait_group 2
// releases exactly chunk c. No CTA barriers; buffers are warp-private.
template<int NS, int NCH, int KS>
__device__ __forceinline__ void run_pass(const uint32_t* __restrict__ gWslice,
                                         const uint32_t* __restrict__ nextWslice,
                                         const char* smem, uint32_t warpB_s,
                                         const char* warpB_c, int lane,
                                         float acc[][4][2][4], int& phase) {
    #pragma unroll
    for (int s = 0; s < NS; s++)
        #pragma unroll
        for (int mt = 0; mt < 4; mt++)
            #pragma unroll
            for (int ntl = 0; ntl < 2; ntl++)
                #pragma unroll
                for (int j = 0; j < 4; j++) acc[s][mt][ntl][j] = 0.0f;

    const uint32_t* src = gWslice + 2 * 4096;   // chunk c+2 source (induction)
    int bufc = phase;
    #pragma unroll 1
    for (int c = 0; c < NCH; c++) {
        int ibuf = bufc + 2; if (ibuf >= 3) ibuf -= 3;
        if (c < NCH - 2) {
            issue_slice(warpB_s + (uint32_t)ibuf * 2048u, src, lane);
            src += 4096;
            asm volatile("cp.async.wait_group 2;" ::: "memory");   // chunk c done
        } else if (nextWslice) {
            issue_slice(warpB_s + (uint32_t)ibuf * 2048u, nextWslice + (c + 2 - NCH) * 4096, lane);
            asm volatile("cp.async.wait_group 2;" ::: "memory");
        } else if (c == NCH - 2) {
            asm volatile("cp.async.wait_group 1;" ::: "memory");
        } else {
            asm volatile("cp.async.wait_group 0;" ::: "memory");
        }

        const char* bb = warpB_c + bufc * 2048;

        #pragma unroll
        for (int kk = 0; kk < KS; kk++) {
            const int kkg = c * KS + kk;
            uint32_t a[4][4];
            #pragma unroll
            for (int mt = 0; mt < 4; mt++) {
                uint4 v = *(const uint4*)(smem + SMEM_A +
                    (uint32_t)(((mt * 32 + kkg) * 32) + (lane ^ (kkg & 7))) * 16u);
                a[mt][0] = v.x; a[mt][1] = v.y; a[mt][2] = v.z; a[mt][3] = v.w;
            }
            #pragma unroll
            for (int s = 0; s < NS; s++) {
                uint4 bv = *(const uint4*)(bb + (s * KS + kk) * 512 + lane * 16);
                uint32_t b0[2] = {bv.x, bv.y};
                uint32_t b1[2] = {bv.z, bv.w};
                #pragma unroll
                for (int mt = 0; mt < 4; mt++) {
                    mma_tf32(acc[s][mt][0], a[mt], b0);
                    mma_tf32(acc[s][mt][1], a[mt], b1);
                }
            }
        }
        bufc++; if (bufc == 3) bufc = 0;
    }
    phase = bufc;
}

// ---------------- main fused kernel ----------------
__global__ void __launch_bounds__(256, 2) treelstm_main(
    const float* __restrict__ h_bot, const float* __restrict__ c_bot,
    const float* __restrict__ h_buf, const float* __restrict__ c_buf,
    const float* __restrict__ bias,  float* __restrict__ out) {
    extern __shared__ char smem[];
    const uint32_t sbase = smem_u32(smem);

    const int tid = threadIdx.x, wid = tid >> 5, lane = tid & 31;
    const int g = lane >> 2, tig = lane & 3;
    const int wq = wid;                          // warp owns N-cols [wq*16, wq*16+16)
    const int blk = blockIdx.x;
    const int mbase = blk * 64;

    const uint32_t warpB_s = sbase + SMEM_B + (uint32_t)wid * 6144u;
    const char*    warpB_c = smem + SMEM_B + wid * 6144;

    // per-pass slice base pointers for this warp
    const uint32_t* w0 = g_Bpack + wq * 512;            // pass0
    const uint32_t* w1 = g_Bpack + 65536 + wq * 512;    // pass1
    const uint32_t* w2 = g_Bpack + 131072 + wq * 512;   // pass2

    // preload this warp's slices for pass0 chunks 0,1 (entry invariant)
    issue_slice(warpB_s,         w0,        lane);
    issue_slice(warpB_s + 2048u, w0 + 4096, lane);

    // ---- gather X = [h_l | h_r] into fragment-packed A (tf32) ----
    // 64 rows x 2 sources = 128 warp-jobs
    for (int j = wid; j < 128; j += 8) {
        int src = j & 1, r = j >> 1;
        int m = mbase + r;
        int map = src ? g_rowmap_r[m] : g_rowmap_l[m];
        const float* sp = ((map < 0) ? h_buf : h_bot) + (size_t)(uint32_t)(map & 0x7fffffff) * DDIM;
        float4 v = ((const float4*)sp)[lane];
        int k0 = src * 128 + lane * 4;
        char* ab = smem + SMEM_A;
        *(uint32_t*)(ab + a_off(r, k0 + 0)) = f2tf32(v.x);
        *(uint32_t*)(ab + a_off(r, k0 + 1)) = f2tf32(v.y);
        *(uint32_t*)(ab + a_off(r, k0 + 2)) = f2tf32(v.z);
        *(uint32_t*)(ab + a_off(r, k0 + 3)) = f2tf32(v.w);
    }
    __syncthreads();   // the ONLY CTA barrier: A tile visible to all warps

    float acc[2][4][2][4];   // [slot][mt][ntl][frag]
    float creg[4][2][4];
    int phase = 0;

    // ---- pass 0: gates i & u ----
    run_pass<2, 16, 2>(w0, w1, smem, warpB_s, warpB_c, lane, acc, phase);
    #pragma unroll
    for (int mt = 0; mt < 4; mt++)
        #pragma unroll
        for (int ntl = 0; ntl < 2; ntl++) {
            int colg = wq * 16 + ntl * 8 + tig * 2;
            float2 bi = *(const float2*)(bias + colg);         // i: cols 0..127
            float2 bu = *(const float2*)(bias + 256 + colg);   // u: cols 256..383
            creg[mt][ntl][0] = sigf(acc[0][mt][ntl][0] + bi.x) * tanhf_(acc[1][mt][ntl][0] + bu.x);
            creg[mt][ntl][1] = sigf(acc[0][mt][ntl][1] + bi.y) * tanhf_(acc[1][mt][ntl][1] + bu.y);
            creg[mt][ntl][2] = sigf(acc[0][mt][ntl][2] + bi.x) * tanhf_(acc[1][mt][ntl][2] + bu.x);
            creg[mt][ntl][3] = sigf(acc[0][mt][ntl][3] + bi.y) * tanhf_(acc[1][mt][ntl][3] + bu.y);
        }

    // ---- L2-prefetch the c_l/c_r rows this thread gathers after pass 1 ----
    {
        const int colb = wq * 16;
        #pragma unroll
        for (int mt = 0; mt < 4; mt++) {
            int r0 = mt * 16 + g;
            int ml0 = g_rowmap_l[mbase + r0], ml1 = g_rowmap_l[mbase + r0 + 8];
            int mr0 = g_rowmap_r[mbase + r0], mr1 = g_rowmap_r[mbase + r0 + 8];
            pf_l2(((ml0 < 0) ? c_buf : c_bot) + (size_t)(uint32_t)(ml0 & 0x7fffffff) * DDIM + colb);
            pf_l2(((ml1 < 0) ? c_buf : c_bot) + (size_t)(uint32_t)(ml1 & 0x7fffffff) * DDIM + colb);
            pf_l2(((mr0 < 0) ? c_buf : c_bot) + (size_t)(uint32_t)(mr0 & 0x7fffffff) * DDIM + colb);
            pf_l2(((mr1 < 0) ? c_buf : c_bot) + (size_t)(uint32_t)(mr1 & 0x7fffffff) * DDIM + colb);
        }
    }

    // ---- pass 1: f_l & f_r together ----
    run_pass<2, 16, 2>(w1, w2, smem, warpB_s, warpB_c, lane, acc, phase);
    #pragma unroll
    for (int mt = 0; mt < 4; mt++) {
        int r0 = mt * 16 + g;
        int ml0 = g_rowmap_l[mbase + r0], ml1 = g_rowmap_l[mbase + r0 + 8];
        int mr0 = g_rowmap_r[mbase + r0], mr1 = g_rowmap_r[mbase + r0 + 8];
        const float* cl0 = ((ml0 < 0) ? c_buf : c_bot) + (size_t)(uint32_t)(ml0 & 0x7fffffff) * DDIM;
        const float* cl1 = ((ml1 < 0) ? c_buf : c_bot) + (size_t)(uint32_t)(ml1 & 0x7fffffff) * DDIM;
        const float* cr0 = ((mr0 < 0) ? c_buf : c_bot) + (size_t)(uint32_t)(mr0 & 0x7fffffff) * DDIM;
        const float* cr1 = ((mr1 < 0) ? c_buf : c_bot) + (size_t)(uint32_t)(mr1 & 0x7fffffff) * DDIM;
        #pragma unroll
        for (int ntl = 0; ntl < 2; ntl++) {
            int colg = wq * 16 + ntl * 8 + tig * 2;
            float2 bl = *(const float2*)(bias + 384 + colg);   // f_l
            float2 br = *(const float2*)(bias + 512 + colg);   // f_r
            float2 vl0 = *(const float2*)(cl0 + colg);
            float2 vl1 = *(const float2*)(cl1 + colg);
            float2 vr0 = *(const float2*)(cr0 + colg);
            float2 vr1 = *(const float2*)(cr1 + colg);
            creg[mt][ntl][0] = fmaf(sigf(acc[0][mt][ntl][0] + bl.x), vl0.x, creg[mt][ntl][0]);
            creg[mt][ntl][1] = fmaf(sigf(acc[0][mt][ntl][1] + bl.y), vl0.y, creg[mt][ntl][1]);
            creg[mt][ntl][2] = fmaf(sigf(acc[0][mt][ntl][2] + bl.x), vl1.x, creg[mt][ntl][2]);
            creg[mt][ntl][3] = fmaf(sigf(acc[0][mt][ntl][3] + bl.y), vl1.y, creg[mt][ntl][3]);
            creg[mt][ntl][0] = fmaf(sigf(acc[1][mt][ntl][0] + br.x), vr0.x, creg[mt][ntl][0]);
            creg[mt][ntl][1] = fmaf(sigf(acc[1][mt][ntl][1] + br.y), vr0.y, creg[mt][ntl][1]);
            creg[mt][ntl][2] = fmaf(sigf(acc[1][mt][ntl][2] + br.x), vr1.x, creg[mt][ntl][2]);
            creg[mt][ntl][3] = fmaf(sigf(acc[1][mt][ntl][3] + br.y), vr1.y, creg[mt][ntl][3]);
        }
    }

    // ---- pass 2: o -> finalize h, c ----
    run_pass<1, 8, 4>(w2, nullptr, smem, warpB_s, warpB_c, lane, acc, phase);
    #pragma unroll
    for (int mt = 0; mt < 4; mt++) {
        size_t m0 = (size_t)(mbase + mt * 16 + g);
        size_t m1 = m0 + 8;
        #pragma unroll
        for (int ntl = 0; ntl < 2; ntl++) {
            int colg = wq * 16 + ntl * 8 + tig * 2;
            float2 bo = *(const float2*)(bias + 128 + colg);   // o: cols 128..255
            float2 h0, h1, c0, c1;
            c0.x = creg[mt][ntl][0]; h0.x = sigf(acc[0][mt][ntl][0] + bo.x) * tanhf_(c0.x);
            c0.y = creg[mt][ntl][1]; h0.y = sigf(acc[0][mt][ntl][1] + bo.y) * tanhf_(c0.y);
            c1.x = creg[mt][ntl][2]; h1.x = sigf(acc[0][mt][ntl][2] + bo.x) * tanhf_(c1.x);
            c1.y = creg[mt][ntl][3]; h1.y = sigf(acc[0][mt][ntl][3] + bo.y) * tanhf_(c1.y);
            *(float2*)(out + m0 * DDIM + colg) = h0;
            *(float2*)(out + m1 * DDIM + colg) = h1;
            *(float2*)(out + (size_t)MROWS * DDIM + m0 * DDIM + colg) = c0;
            *(float2*)(out + (size_t)MROWS * DDIM + m1 * DDIM + colg) = c1;
        }
    }
}

// ---------------- launch ----------------
extern "C" void kernel_launch(void* const* d_in, const int* in_sizes, int n_in,
                              void* d_out, int out_size) {
    const float* h_bot = (const float*)d_in[0];
    const float* c_bot = (const float*)d_in[1];
    const float* h_buf = (const float*)d_in[2];
    const float* c_buf = (const float*)d_in[3];
    const float* W     = (const float*)d_in[4];
    const float* b     = (const float*)d_in[5];
    const int* bf0 = (const int*)d_in[6];
    const int* bt0 = (const int*)d_in[7];
    const int* pf0 = (const int*)d_in[8];
    const int* pt0 = (const int*)d_in[9];
    const int* bf1 = (const int*)d_in[10];
    const int* bt1 = (const int*)d_in[11];
    const int* pf1 = (const int*)d_in[12];
    const int* pt1 = (const int*)d_in[13];
    float* out = (float*)d_out;

    cudaFuncSetAttribute(treelstm_main, cudaFuncAttributeMaxDynamicSharedMemorySize, SMEM_TOTAL);

    prep_all<<<640, 256>>>(W, bf0, bt0, pf0, pt0, bf1, bt1, pf1, pt1);
    treelstm_main<<<MROWS / 64, 256, SMEM_TOTAL>>>(h_bot, c_bot, h_buf, c_buf, b, out);
}

// round 15
// speedup vs baseline: 1.7000x; 1.0066x over previous
#include <cuda_runtime.h>
#include <cstdint>

#define DDIM   128
#define MROWS  131072
#define KHALF  (MROWS/2)

// ---------------- device scratch ----------------
__device__ int      g_rowmap_l[MROWS];
__device__ int      g_rowmap_r[MROWS];
// pass-major pre-swizzled tf32 B fragments, warp-sliced:
//  chunk = 4096 words (16KB); within chunk: 8 slices of 512 words (one per warp wq)
//  slice: 4 lines x 128 words; line = slot*KS + kk; within line: lane*4 + ntl*2 + ws
//  pass0 {i,u}:    words [0,      65536)  16 chunks (K=16, NS=2, KS=2)
//  pass1 {fl,fr}:  words [65536, 131072)  16 chunks (K=16, NS=2, KS=2)
//  pass2 {o}:      words [131072,163840)   8 chunks (K=32, NS=1, KS=4)
__device__ uint32_t g_Bpack[163840];

// ---------------- helpers ----------------
__device__ __forceinline__ uint32_t smem_u32(const void* p) {
    uint32_t a;
    asm("{ .reg .u64 t; cvta.to.shared.u64 t, %1; cvt.u32.u64 %0, t; }" : "=r"(a) : "l"(p));
    return a;
}
__device__ __forceinline__ uint32_t f2tf32(float f) {
    uint32_t r; asm("cvt.rna.tf32.f32 %0, %1;" : "=r"(r) : "f"(f)); return r;
}
__device__ __forceinline__ float ex2f(float x) {
    float y; asm("ex2.approx.f32 %0, %1;" : "=f"(y) : "f"(x)); return y;
}
__device__ __forceinline__ float rcpf(float x) {
    float y; asm("rcp.approx.f32 %0, %1;" : "=f"(y) : "f"(x)); return y;
}
__device__ __forceinline__ float sigf(float x) {
    return rcpf(1.0f + ex2f(-1.4426950408889634f * x));
}
__device__ __forceinline__ float tanhf_(float x) {
    return fmaf(2.0f, rcpf(1.0f + ex2f(-2.8853900817779268f * x)), -1.0f);
}
__device__ __forceinline__ void mma_tf32(float* d, const uint32_t* a, const uint32_t* b) {
    asm volatile(
        "mma.sync.aligned.m16n8k8.row.col.f32.tf32.tf32.f32 "
        "{%0,%1,%2,%3}, {%4,%5,%6,%7}, {%8,%9}, {%0,%1,%2,%3};"
        : "+f"(d[0]), "+f"(d[1]), "+f"(d[2]), "+f"(d[3])
        : "r"(a[0]), "r"(a[1]), "r"(a[2]), "r"(a[3]), "r"(b[0]), "r"(b[1]));
}
__device__ __forceinline__ void cpa16(uint32_t dst, const uint32_t* src) {
    asm volatile("cp.async.cg.shared.global [%0], [%1], 16;" :: "r"(dst), "l"(src));
}
__device__ __forceinline__ void cp_commit() {
    asm volatile("cp.async.commit_group;" ::: "memory");
}
__device__ __forceinline__ void pf_l2(const void* p) {
    asm volatile("prefetch.global.L2 [%0];" :: "l"(p));
}

// ---------------- SMEM layout (114688 B exactly -> 2 CTAs/SM) ----------------
#define SMEM_A     0          // 64x256 tf32 fragment-packed = 65536 B
#define SMEM_B     65536      // 8 warps x 3 bufs x 2048 B = 49152 B
#define SMEM_TOTAL 114688

// A pack byte offset (relative to SMEM_A) for element (r,k), r in [0,64)
__device__ __forceinline__ uint32_t a_off(int r, int k) {
    int mt = r >> 4, kk = k >> 3;
    int lane = ((r & 7) << 2) | (k & 3);
    int slot = ((r >> 3) & 1) | (((k >> 2) & 1) << 1);
    return (uint32_t)((((mt << 5) + kk) << 5) + (lane ^ (kk & 7))) * 16u + (uint32_t)slot * 4u;
}

// ---------------- single merged prep kernel ----------------
__global__ void prep_all(const float* __restrict__ W,
                         const int* __restrict__ bf0, const int* __restrict__ bt0,
                         const int* __restrict__ pf0, const int* __restrict__ pt0,
                         const int* __restrict__ bf1, const int* __restrict__ bt1,
                         const int* __restrict__ pf1, const int* __restrict__ pt1) {
    int idx = blockIdx.x * blockDim.x + threadIdx.x;
    if (idx < KHALF) {
        g_rowmap_l[bt0[idx]] = bf0[idx];
        g_rowmap_l[pt0[idx]] = (int)((uint32_t)pf0[idx] | 0x80000000u);
        g_rowmap_r[bt1[idx]] = bf1[idx];
        g_rowmap_r[pt1[idx]] = (int)((uint32_t)pf1[idx] | 0x80000000u);
    }
    if (idx < 256 * 640) {
        int k = idx / 640, col = idx % 640;
        int gate = col >> 7, n = col & 127;     // gates: 0:i 1:o 2:u 3:f_l 4:f_r
        int pass, slot;
        if      (gate == 0) { pass = 0; slot = 0; }
        else if (gate == 2) { pass = 0; slot = 1; }
        else if (gate == 3) { pass = 1; slot = 0; }
        else if (gate == 4) { pass = 1; slot = 1; }
        else                { pass = 2; slot = 0; }
        int nt = n >> 3;               // 0..15
        int p  = nt >> 1;              // warp slice 0..7
        int ntl = nt & 1;
        int nl = n & 7;
        int kl = k & 7;
        int lane = (nl << 2) | (kl & 3);
        int ws = (kl >> 2) & 1;
        int off;
        if (pass < 2) {  // K-chunk 16: chunk = k>>4, kk = (k>>3)&1, KS=2
            int chunk = k >> 4, kk = (k >> 3) & 1;
            off = pass * 65536 + chunk * 4096 + p * 512
                + (slot * 2 + kk) * 128 + lane * 4 + ntl * 2 + ws;
        } else {         // K-chunk 32: chunk = k>>5, kk = (k>>3)&3, KS=4
            int chunk = k >> 5, kk = (k >> 3) & 3;
            off = 131072 + chunk * 4096 + p * 512
                + kk * 128 + lane * 4 + ntl * 2 + ws;
        }
        g_Bpack[off] = f2tf32(W[idx]);
    }
}

// ---------------- warp-private slice fill ----------------
// one slice = 512 words = 2048 B = 128 uint4 = 4 per lane
__device__ __forceinline__ void issue_slice(uint32_t sdst, const uint32_t* src, int lane) {
    #pragma unroll
    for (int i = 0; i < 4; i++) {
        int unit = i * 32 + lane;
        cpa16(sdst + (uint32_t)unit * 16u, src + unit * 4);
    }
    cp_commit();
}

// ---------------- barrier-free warp-private pass ----------------
// Entry invariant (per warp): slices for chunks 0,1 of this pass are in flight
// to buffers phase, phase+1 (two cp.async groups pending, oldest = chunk 0).
// Each iter: ISSUE chunk c+2 (into buffer holding consumed chunk c-1), THEN
// wait for chunk c, then compute. Pending after issue = 3 -> wait_group 2
// releases exactly chunk c. No CTA barriers; buffers are warp-private.
// Chunk loop unrolled in groups of U with U*KS == 8 so that kkg mod 8 is
// compile-time: the A-swizzle XOR lane^(kkg&7) becomes loop-invariant and
// A addresses reduce to induction + immediate offsets.
template<int NS, int NCH, int KS, int U>
__device__ __forceinline__ void run_pass(const uint32_t* __restrict__ gWslice,
                                         const uint32_t* __restrict__ nextWslice,
                                         const char* smem, uint32_t warpB_s,
                                         const char* warpB_c, int lane,
                                         float acc[][4][2][4], int& phase) {
    static_assert(U * KS == 8, "unroll group must cover 8 k8-steps");
    #pragma unroll
    for (int s = 0; s < NS; s++)
        #pragma unroll
        for (int mt = 0; mt < 4; mt++)
            #pragma unroll
            for (int ntl = 0; ntl < 2; ntl++)
                #pragma unroll
                for (int j = 0; j < 4; j++) acc[s][mt][ntl][j] = 0.0f;

    const uint32_t* src = gWslice + 2 * 4096;   // chunk c+2 source (induction)
    int bufc = phase;
    #pragma unroll 1
    for (int c2 = 0; c2 < NCH / U; c2++) {
        const int kbase = c2 * 8;               // kkg = kbase + kq, kq compile-time
        #pragma unroll
        for (int cc = 0; cc < U; cc++) {
            const int c = c2 * U + cc;
            int ibuf = bufc + 2; if (ibuf >= 3) ibuf -= 3;
            if (c < NCH - 2) {
                issue_slice(warpB_s + (uint32_t)ibuf * 2048u, src, lane);
                src += 4096;
                asm volatile("cp.async.wait_group 2;" ::: "memory");   // chunk c done
            } else if (nextWslice) {
                issue_slice(warpB_s + (uint32_t)ibuf * 2048u, nextWslice + (c + 2 - NCH) * 4096, lane);
                asm volatile("cp.async.wait_group 2;" ::: "memory");
            } else if (c == NCH - 2) {
                asm volatile("cp.async.wait_group 1;" ::: "memory");
            } else {
                asm volatile("cp.async.wait_group 0;" ::: "memory");
            }

            const char* bb = warpB_c + bufc * 2048;

            #pragma unroll
            for (int kk = 0; kk < KS; kk++) {
                const int kq = cc * KS + kk;        // compile-time 0..7
                uint32_t a[4][4];
                #pragma unroll
                for (int mt = 0; mt < 4; mt++) {
                    uint4 v = *(const uint4*)(smem + SMEM_A +
                        (uint32_t)(((mt * 32 + kbase + kq) * 32) + (lane ^ (kq & 7))) * 16u);
                    a[mt][0] = v.x; a[mt][1] = v.y; a[mt][2] = v.z; a[mt][3] = v.w;
                }
                #pragma unroll
                for (int s = 0; s < NS; s++) {
                    uint4 bv = *(const uint4*)(bb + (s * KS + kk) * 512 + lane * 16);
                    uint32_t b0[2] = {bv.x, bv.y};
                    uint32_t b1[2] = {bv.z, bv.w};
                    #pragma unroll
                    for (int mt = 0; mt < 4; mt++) {
                        mma_tf32(acc[s][mt][0], a[mt], b0);
                        mma_tf32(acc[s][mt][1], a[mt], b1);
                    }
                }
            }
            bufc++; if (bufc == 3) bufc = 0;
        }
    }
    phase = bufc;
}

// ---------------- main fused kernel ----------------
__global__ void __launch_bounds__(256, 2) treelstm_main(
    const float* __restrict__ h_bot, const float* __restrict__ c_bot,
    const float* __restrict__ h_buf, const float* __restrict__ c_buf,
    const float* __restrict__ bias,  float* __restrict__ out) {
    extern __shared__ char smem[];
    const uint32_t sbase = smem_u32(smem);

    const int tid = threadIdx.x, wid = tid >> 5, lane = tid & 31;
    const int g = lane >> 2, tig = lane & 3;
    const int wq = wid;                          // warp owns N-cols [wq*16, wq*16+16)
    const int blk = blockIdx.x;
    const int mbase = blk * 64;

    const uint32_t warpB_s = sbase + SMEM_B + (uint32_t)wid * 6144u;
    const char*    warpB_c = smem + SMEM_B + wid * 6144;

    // per-pass slice base pointers for this warp
    const uint32_t* w0 = g_Bpack + wq * 512;            // pass0
    const uint32_t* w1 = g_Bpack + 65536 + wq * 512;    // pass1
    const uint32_t* w2 = g_Bpack + 131072 + wq * 512;   // pass2

    // preload this warp's slices for pass0 chunks 0,1 (entry invariant)
    issue_slice(warpB_s,         w0,        lane);
    issue_slice(warpB_s + 2048u, w0 + 4096, lane);

    // ---- gather X = [h_l | h_r] into fragment-packed A (tf32) ----
    // 64 rows x 2 sources = 128 warp-jobs
    for (int j = wid; j < 128; j += 8) {
        int src = j & 1, r = j >> 1;
        int m = mbase + r;
        int map = src ? g_rowmap_r[m] : g_rowmap_l[m];
        const float* sp = ((map < 0) ? h_buf : h_bot) + (size_t)(uint32_t)(map & 0x7fffffff) * DDIM;
        float4 v = ((const float4*)sp)[lane];
        int k0 = src * 128 + lane * 4;
        char* ab = smem + SMEM_A;
        *(uint32_t*)(ab + a_off(r, k0 + 0)) = f2tf32(v.x);
        *(uint32_t*)(ab + a_off(r, k0 + 1)) = f2tf32(v.y);
        *(uint32_t*)(ab + a_off(r, k0 + 2)) = f2tf32(v.z);
        *(uint32_t*)(ab + a_off(r, k0 + 3)) = f2tf32(v.w);
    }
    __syncthreads();   // the ONLY CTA barrier: A tile visible to all warps

    float acc[2][4][2][4];   // [slot][mt][ntl][frag]
    float creg[4][2][4];
    int phase = 0;

    // ---- pass 0: gates i & u ----
    run_pass<2, 16, 2, 4>(w0, w1, smem, warpB_s, warpB_c, lane, acc, phase);
    #pragma unroll
    for (int mt = 0; mt < 4; mt++)
        #pragma unroll
        for (int ntl = 0; ntl < 2; ntl++) {
            int colg = wq * 16 + ntl * 8 + tig * 2;
            float2 bi = *(const float2*)(bias + colg);         // i: cols 0..127
            float2 bu = *(const float2*)(bias + 256 + colg);   // u: cols 256..383
            creg[mt][ntl][0] = sigf(acc[0][mt][ntl][0] + bi.x) * tanhf_(acc[1][mt][ntl][0] + bu.x);
            creg[mt][ntl][1] = sigf(acc[0][mt][ntl][1] + bi.y) * tanhf_(acc[1][mt][ntl][1] + bu.y);
            creg[mt][ntl][2] = sigf(acc[0][mt][ntl][2] + bi.x) * tanhf_(acc[1][mt][ntl][2] + bu.x);
            creg[mt][ntl][3] = sigf(acc[0][mt][ntl][3] + bi.y) * tanhf_(acc[1][mt][ntl][3] + bu.y);
        }

    // ---- L2-prefetch the c_l/c_r rows this thread gathers after pass 1 ----
    {
        const int colb = wq * 16;
        #pragma unroll
        for (int mt = 0; mt < 4; mt++) {
            int r0 = mt * 16 + g;
            int ml0 = g_rowmap_l[mbase + r0], ml1 = g_rowmap_l[mbase + r0 + 8];
            int mr0 = g_rowmap_r[mbase + r0], mr1 = g_rowmap_r[mbase + r0 + 8];
            pf_l2(((ml0 < 0) ? c_buf : c_bot) + (size_t)(uint32_t)(ml0 & 0x7fffffff) * DDIM + colb);
            pf_l2(((ml1 < 0) ? c_buf : c_bot) + (size_t)(uint32_t)(ml1 & 0x7fffffff) * DDIM + colb);
            pf_l2(((mr0 < 0) ? c_buf : c_bot) + (size_t)(uint32_t)(mr0 & 0x7fffffff) * DDIM + colb);
            pf_l2(((mr1 < 0) ? c_buf : c_bot) + (size_t)(uint32_t)(mr1 & 0x7fffffff) * DDIM + colb);
        }
    }

    // ---- pass 1: f_l & f_r together ----
    run_pass<2, 16, 2, 4>(w1, w2, smem, warpB_s, warpB_c, lane, acc, phase);
    #pragma unroll
    for (int mt = 0; mt < 4; mt++) {
        int r0 = mt * 16 + g;
        int ml0 = g_rowmap_l[mbase + r0], ml1 = g_rowmap_l[mbase + r0 + 8];
        int mr0 = g_rowmap_r[mbase + r0], mr1 = g_rowmap_r[mbase + r0 + 8];
        const float* cl0 = ((ml0 < 0) ? c_buf : c_bot) + (size_t)(uint32_t)(ml0 & 0x7fffffff) * DDIM;
        const float* cl1 = ((ml1 < 0) ? c_buf : c_bot) + (size_t)(uint32_t)(ml1 & 0x7fffffff) * DDIM;
        const float* cr0 = ((mr0 < 0) ? c_buf : c_bot) + (size_t)(uint32_t)(mr0 & 0x7fffffff) * DDIM;
        const float* cr1 = ((mr1 < 0) ? c_buf : c_bot) + (size_t)(uint32_t)(mr1 & 0x7fffffff) * DDIM;
        #pragma unroll
        for (int ntl = 0; ntl < 2; ntl++) {
            int colg = wq * 16 + ntl * 8 + tig * 2;
            float2 bl = *(const float2*)(bias + 384 + colg);   // f_l
            float2 br = *(const float2*)(bias + 512 + colg);   // f_r
            float2 vl0 = *(const float2*)(cl0 + colg);
            float2 vl1 = *(const float2*)(cl1 + colg);
            float2 vr0 = *(const float2*)(cr0 + colg);
            float2 vr1 = *(const float2*)(cr1 + colg);
            creg[mt][ntl][0] = fmaf(sigf(acc[0][mt][ntl][0] + bl.x), vl0.x, creg[mt][ntl][0]);
            creg[mt][ntl][1] = fmaf(sigf(acc[0][mt][ntl][1] + bl.y), vl0.y, creg[mt][ntl][1]);
            creg[mt][ntl][2] = fmaf(sigf(acc[0][mt][ntl][2] + bl.x), vl1.x, creg[mt][ntl][2]);
            creg[mt][ntl][3] = fmaf(sigf(acc[0][mt][ntl][3] + bl.y), vl1.y, creg[mt][ntl][3]);
            creg[mt][ntl][0] = fmaf(sigf(acc[1][mt][ntl][0] + br.x), vr0.x, creg[mt][ntl][0]);
            creg[mt][ntl][1] = fmaf(sigf(acc[1][mt][ntl][1] + br.y), vr0.y, creg[mt][ntl][1]);
            creg[mt][ntl][2] = fmaf(sigf(acc[1][mt][ntl][2] + br.x), vr1.x, creg[mt][ntl][2]);
            creg[mt][ntl][3] = fmaf(sigf(acc[1][mt][ntl][3] + br.y), vr1.y, creg[mt][ntl][3]);
        }
    }

    // ---- pass 2: o -> finalize h, c ----
    run_pass<1, 8, 4, 2>(w2, nullptr, smem, warpB_s, warpB_c, lane, acc, phase);
    #pragma unroll
    for (int mt = 0; mt < 4; mt++) {
        size_t m0 = (size_t)(mbase + mt * 16 + g);
        size_t m1 = m0 + 8;
        #pragma unroll
        for (int ntl = 0; ntl < 2; ntl++) {
            int colg = wq * 16 + ntl * 8 + tig * 2;
            float2 bo = *(const float2*)(bias + 128 + colg);   // o: cols 128..255
            float2 h0, h1, c0, c1;
            c0.x = creg[mt][ntl][0]; h0.x = sigf(acc[0][mt][ntl][0] + bo.x) * tanhf_(c0.x);
            c0.y = creg[mt][ntl][1]; h0.y = sigf(acc[0][mt][ntl][1] + bo.y) * tanhf_(c0.y);
            c1.x = creg[mt][ntl][2]; h1.x = sigf(acc[0][mt][ntl][2] + bo.x) * tanhf_(c1.x);
            c1.y = creg[mt][ntl][3]; h1.y = sigf(acc[0][mt][ntl][3] + bo.y) * tanhf_(c1.y);
            *(float2*)(out + m0 * DDIM + colg) = h0;
            *(float2*)(out + m1 * DDIM + colg) = h1;
            *(float2*)(out + (size_t)MROWS * DDIM + m0 * DDIM + colg) = c0;
            *(float2*)(out + (size_t)MROWS * DDIM + m1 * DDIM + colg) = c1;
        }
    }
}

// ---------------- launch ----------------
extern "C" void kernel_launch(void* const* d_in, const int* in_sizes, int n_in,
                              void* d_out, int out_size) {
    const float* h_bot = (const float*)d_in[0];
    const float* c_bot = (const float*)d_in[1];
    const float* h_buf = (const float*)d_in[2];
    const float* c_buf = (const float*)d_in[3];
    const float* W     = (const float*)d_in[4];
    const float* b     = (const float*)d_in[5];
    const int* bf0 = (const int*)d_in[6];
    const int* bt0 = (const int*)d_in[7];
    const int* pf0 = (const int*)d_in[8];
    const int* pt0 = (const int*)d_in[9];
    const int* bf1 = (const int*)d_in[10];
    const int* bt1 = (const int*)d_in[11];
    const int* pf1 = (const int*)d_in[12];
    const int* pt1 = (const int*)d_in[13];
    float* out = (float*)d_out;

    cudaFuncSetAttribute(treelstm_main, cudaFuncAttributeMaxDynamicSharedMemorySize, SMEM_TOTAL);

    prep_all<<<640, 256>>>(W, bf0, bt0, pf0, pt0, bf1, bt1, pf1, pt1);
    treelstm_main<<<MROWS / 64, 256, SMEM_TOTAL>>>(h_bot, c_bot, h_buf, c_buf, b, out);
}

// round 16
// speedup vs baseline: 2.2994x; 1.3526x over previous
#include <cuda_runtime.h>
#include <cuda_fp16.h>
#include <cstdint>

#define DDIM   128
#define MROWS  131072
#define KHALF  (MROWS/2)

// ---------------- device scratch ----------------
__device__ int            g_rowmap_l[MROWS];
__device__ int            g_rowmap_r[MROWS];
// pass-major fp16 B fragments, warp-sliced. half-indexed:
//  chunk = 8192 halfs (16KB); 8 slices of 1024 halfs (2KB) per chunk (one per warp)
//  pass0 {i,u}:   halfs [0,      65536)   8 chunks (K=32, NS=2, KS=2 k16-steps)
//  pass1 {fl,fr}: halfs [65536, 131072)   8 chunks (K=32, NS=2, KS=2)
//  pass2 {o}:     halfs [131072,163840)   4 chunks (K=64, NS=1, KS=4)
//  slice layout: [slot]( *512h ) [kk16]( *256h ) [lane]( *8h ) [ntl]( *4h ) [reg]( *2h ) [hb]
__device__ unsigned short g_Bpack[163840];

// ---------------- helpers ----------------
__device__ __forceinline__ uint32_t smem_u32(const void* p) {
    uint32_t a;
    asm("{ .reg .u64 t; cvta.to.shared.u64 t, %1; cvt.u32.u64 %0, t; }" : "=r"(a) : "l"(p));
    return a;
}
__device__ __forceinline__ float ex2f(float x) {
    float y; asm("ex2.approx.f32 %0, %1;" : "=f"(y) : "f"(x)); return y;
}
__device__ __forceinline__ float rcpf(float x) {
    float y; asm("rcp.approx.f32 %0, %1;" : "=f"(y) : "f"(x)); return y;
}
__device__ __forceinline__ float sigf(float x) {
    return rcpf(1.0f + ex2f(-1.4426950408889634f * x));
}
__device__ __forceinline__ float tanhf_(float x) {
    return fmaf(2.0f, rcpf(1.0f + ex2f(-2.8853900817779268f * x)), -1.0f);
}
// mma.m16n8k16 f16 inputs, f32 accumulate
__device__ __forceinline__ void mma_f16(float* d, const uint32_t* a, const uint32_t* b) {
    asm volatile(
        "mma.sync.aligned.m16n8k16.row.col.f32.f16.f16.f32 "
        "{%0,%1,%2,%3}, {%4,%5,%6,%7}, {%8,%9}, {%0,%1,%2,%3};"
        : "+f"(d[0]), "+f"(d[1]), "+f"(d[2]), "+f"(d[3])
        : "r"(a[0]), "r"(a[1]), "r"(a[2]), "r"(a[3]), "r"(b[0]), "r"(b[1]));
}
__device__ __forceinline__ void cpa16(uint32_t dst, const void* src) {
    asm volatile("cp.async.cg.shared.global [%0], [%1], 16;" :: "r"(dst), "l"(src));
}
__device__ __forceinline__ void cp_commit() {
    asm volatile("cp.async.commit_group;" ::: "memory");
}
__device__ __forceinline__ void pf_l2(const void* p) {
    asm volatile("prefetch.global.L2 [%0];" :: "l"(p));
}

// ---------------- SMEM layout (99328 B -> 2 CTAs/SM) ----------------
// A: 64 fragment cells (mt 0..3 x k16 0..15), each 528 B (512 data + 16 pad for
//    gather-write bank stagger). cell ci = mt*16+k16 at byte ci*528. 33792 B.
// B: 8 warps x 4 ring buffers x 2048 B = 65536 B.
#define SMEM_A      0
#define A_CELL      528
#define SMEM_B      33792
#define SMEM_TOTAL  99328

// ---------------- single merged prep kernel ----------------
__global__ void prep_all(const float* __restrict__ W,
                         const int* __restrict__ bf0, const int* __restrict__ bt0,
                         const int* __restrict__ pf0, const int* __restrict__ pt0,
                         const int* __restrict__ bf1, const int* __restrict__ bt1,
                         const int* __restrict__ pf1, const int* __restrict__ pt1) {
    int idx = blockIdx.x * blockDim.x + threadIdx.x;
    if (idx < KHALF) {
        g_rowmap_l[bt0[idx]] = bf0[idx];
        g_rowmap_l[pt0[idx]] = (int)((uint32_t)pf0[idx] | 0x80000000u);
        g_rowmap_r[bt1[idx]] = bf1[idx];
        g_rowmap_r[pt1[idx]] = (int)((uint32_t)pf1[idx] | 0x80000000u);
    }
    if (idx < 256 * 640) {
        int k = idx / 640, col = idx % 640;
        int gate = col >> 7, n = col & 127;     // gates: 0:i 1:o 2:u 3:f_l 4:f_r
        int pass, slot;
        if      (gate == 0) { pass = 0; slot = 0; }
        else if (gate == 2) { pass = 0; slot = 1; }
        else if (gate == 3) { pass = 1; slot = 0; }
        else if (gate == 4) { pass = 1; slot = 1; }
        else                { pass = 2; slot = 0; }
        int p   = n >> 4;              // warp slice 0..7
        int ntl = (n >> 3) & 1;        // n8 block within slice
        int g   = n & 7;               // col within n8
        int koff = k & 15;
        int reg  = koff >> 3;          // b0/b1 (k-half)
        int tig  = (koff & 7) >> 1;
        int hb   = k & 1;
        int lane = g * 4 + tig;
        int off;
        if (pass < 2) {   // K-chunk 32: chunk=k>>5, kk16=(k>>4)&1
            int chunk = k >> 5, kk16 = (k >> 4) & 1;
            off = pass * 65536 + chunk * 8192 + p * 1024
                + slot * 512 + kk16 * 256 + lane * 8 + ntl * 4 + reg * 2 + hb;
        } else {          // K-chunk 64: chunk=k>>6, kk16=(k>>4)&3
            int chunk = k >> 6, kk16 = (k >> 4) & 3;
            off = 131072 + chunk * 8192 + p * 1024
                + kk16 * 256 + lane * 8 + ntl * 4 + reg * 2 + hb;
        }
        __half hv = __float2half_rn(W[idx]);
        g_Bpack[off] = *(unsigned short*)&hv;
    }
}

// ---------------- warp-private slice fill ----------------
// one slice = 2048 B = 128 uint4 = 4 per lane
__device__ __forceinline__ void issue_slice(uint32_t sdst, const char* src, int lane) {
    #pragma unroll
    for (int i = 0; i < 4; i++) {
        int unit = i * 32 + lane;
        cpa16(sdst + (uint32_t)unit * 16u, src + unit * 16);
    }
    cp_commit();
}

// ---------------- barrier-free warp-private pass (ring-4) ----------------
// Entry invariant (per warp): slices for chunks 0,1,2 of this pass are in
// flight to ring buffers phase..phase+2 (3 cp.async groups pending, oldest =
// chunk 0). Each iter: issue chunk c+3 (buffer holding consumed chunk c-1),
// wait chunk c (wait_group 3: 4 pending after issue), compute c.
// Runway(c+3) = compute(c..c+2). No CTA barriers; buffers warp-private.
template<int NS, int NCH, int KS>
__device__ __forceinline__ void run_pass(const char* __restrict__ gWslice,
                                         const char* __restrict__ nextWslice,
                                         const char* smem, uint32_t warpB_s,
                                         const char* warpB_c, int lane,
                                         float acc[][4][2][4], int& phase) {
    #pragma unroll
    for (int s = 0; s < NS; s++)
        #pragma unroll
        for (int mt = 0; mt < 4; mt++)
            #pragma unroll
            for (int ntl = 0; ntl < 2; ntl++)
                #pragma unroll
                for (int j = 0; j < 4; j++) acc[s][mt][ntl][j] = 0.0f;

    const char* src = gWslice + 3 * 16384;   // chunk c+3 source (induction)
    int bufc = phase;
    int aoff = 0;                            // byte offset of k16-cell row for chunk c
    #pragma unroll 1
    for (int c = 0; c < NCH; c++) {
        int ibuf = (bufc + 3) & 3;
        if (c < NCH - 3) {
            issue_slice(warpB_s + (uint32_t)ibuf * 2048u, src, lane);
            src += 16384;
            asm volatile("cp.async.wait_group 3;" ::: "memory");
        } else if (nextWslice) {
            issue_slice(warpB_s + (uint32_t)ibuf * 2048u, nextWslice + (c + 3 - NCH) * 16384, lane);
            asm volatile("cp.async.wait_group 3;" ::: "memory");
        } else if (c == NCH - 3) {
            asm volatile("cp.async.wait_group 2;" ::: "memory");
        } else if (c == NCH - 2) {
            asm volatile("cp.async.wait_group 1;" ::: "memory");
        } else {
            asm volatile("cp.async.wait_group 0;" ::: "memory");
        }

        const char* bb = warpB_c + bufc * 2048;

        #pragma unroll
        for (int kk = 0; kk < KS; kk++) {
            const char* acell = smem + SMEM_A + aoff + kk * A_CELL + lane * 16;
            uint32_t a[4][4];
            #pragma unroll
            for (int mt = 0; mt < 4; mt++) {
                uint4 v = *(const uint4*)(acell + mt * (16 * A_CELL));
                a[mt][0] = v.x; a[mt][1] = v.y; a[mt][2] = v.z; a[mt][3] = v.w;
            }
            #pragma unroll
            for (int s = 0; s < NS; s++) {
                uint4 bv = *(const uint4*)(bb + s * 1024 + kk * 512 + lane * 16);
                uint32_t b0[2] = {bv.x, bv.y};   // ntl 0
                uint32_t b1[2] = {bv.z, bv.w};   // ntl 1
                #pragma unroll
                for (int mt = 0; mt < 4; mt++) {
                    mma_f16(acc[s][mt][0], a[mt], b0);
                    mma_f16(acc[s][mt][1], a[mt], b1);
                }
            }
        }
        aoff += KS * A_CELL;
        bufc = (bufc + 1) & 3;
    }
    phase = bufc;
}

// ---------------- main fused kernel ----------------
__global__ void __launch_bounds__(256, 2) treelstm_main(
    const float* __restrict__ h_bot, const float* __restrict__ c_bot,
    const float* __restrict__ h_buf, const float* __restrict__ c_buf,
    const float* __restrict__ bias,  float* __restrict__ out) {
    extern __shared__ char smem[];
    const uint32_t sbase = smem_u32(smem);

    const int tid = threadIdx.x, wid = tid >> 5, lane = tid & 31;
    const int g = lane >> 2, tig = lane & 3;
    const int wq = wid;                          // warp owns N-cols [wq*16, wq*16+16)
    const int blk = blockIdx.x;
    const int mbase = blk * 64;

    const uint32_t warpB_s = sbase + SMEM_B + (uint32_t)wid * 8192u;
    const char*    warpB_c = smem + SMEM_B + wid * 8192;

    // per-pass slice base pointers (bytes) for this warp
    const char* w0 = (const char*)g_Bpack + wq * 2048;              // pass0
    const char* w1 = (const char*)g_Bpack + 131072 + wq * 2048;     // pass1
    const char* w2 = (const char*)g_Bpack + 262144 + wq * 2048;     // pass2

    // preload pass0 chunks 0,1,2 (ring-4 entry invariant)
    issue_slice(warpB_s,         w0,         lane);
    issue_slice(warpB_s + 2048u, w0 + 16384, lane);
    issue_slice(warpB_s + 4096u, w0 + 32768, lane);

    // ---- gather X = [h_l | h_r] into fp16 fragment cells ----
    // 64 rows x 2 sources = 128 warp-jobs; thread covers k = 4*lane .. 4*lane+3
    for (int j = wid; j < 128; j += 8) {
        int srcsel = j & 1, r = j >> 1;
        int m = mbase + r;
        int map = srcsel ? g_rowmap_r[m] : g_rowmap_l[m];
        const float* sp = ((map < 0) ? h_buf : h_bot) + (size_t)(uint32_t)(map & 0x7fffffff) * DDIM;
        float4 v = ((const float4*)sp)[lane];
        __half2 h01 = __floats2half2_rn(v.x, v.y);   // k, k+1
        __half2 h23 = __floats2half2_rn(v.z, v.w);   // k+2, k+3
        // destination fragment coordinates (k = srcsel*128 + 4*lane + ...)
        int kg    = srcsel * 128 + lane * 4;
        int k16   = kg >> 4;
        int khalf = (kg >> 3) & 1;
        int tg    = (kg & 7) >> 1;                   // tig of first word
        int mt    = r >> 4;
        int rbit  = (r >> 3) & 1;
        int gg    = r & 7;
        int reg   = rbit + 2 * khalf;
        char* cell = smem + SMEM_A + (mt * 16 + k16) * A_CELL;
        *(uint32_t*)(cell + (gg * 4 + tg)     * 16 + reg * 4) = *(uint32_t*)&h01;
        *(uint32_t*)(cell + (gg * 4 + tg + 1) * 16 + reg * 4) = *(uint32_t*)&h23;
    }
    __syncthreads();   // the ONLY CTA barrier: A tile visible to all warps

    float acc[2][4][2][4];   // [slot][mt][ntl][frag]
    float creg[4][2][4];
    int phase = 0;

    // ---- pass 0: gates i & u ----
    run_pass<2, 8, 2>(w0, w1, smem, warpB_s, warpB_c, lane, acc, phase);
    #pragma unroll
    for (int mt = 0; mt < 4; mt++)
        #pragma unroll
        for (int ntl = 0; ntl < 2; ntl++) {
            int colg = wq * 16 + ntl * 8 + tig * 2;
            float2 bi = *(const float2*)(bias + colg);         // i: cols 0..127
            float2 bu = *(const float2*)(bias + 256 + colg);   // u: cols 256..383
            creg[mt][ntl][0] = sigf(acc[0][mt][ntl][0] + bi.x) * tanhf_(acc[1][mt][ntl][0] + bu.x);
            creg[mt][ntl][1] = sigf(acc[0][mt][ntl][1] + bi.y) * tanhf_(acc[1][mt][ntl][1] + bu.y);
            creg[mt][ntl][2] = sigf(acc[0][mt][ntl][2] + bi.x) * tanhf_(acc[1][mt][ntl][2] + bu.x);
            creg[mt][ntl][3] = sigf(acc[0][mt][ntl][3] + bi.y) * tanhf_(acc[1][mt][ntl][3] + bu.y);
        }

    // ---- L2-prefetch the c_l/c_r rows this thread gathers after pass 1 ----
    {
        const int colb = wq * 16;
        #pragma unroll
        for (int mt = 0; mt < 4; mt++) {
            int r0 = mt * 16 + g;
            int ml0 = g_rowmap_l[mbase + r0], ml1 = g_rowmap_l[mbase + r0 + 8];
            int mr0 = g_rowmap_r[mbase + r0], mr1 = g_rowmap_r[mbase + r0 + 8];
            pf_l2(((ml0 < 0) ? c_buf : c_bot) + (size_t)(uint32_t)(ml0 & 0x7fffffff) * DDIM + colb);
            pf_l2(((ml1 < 0) ? c_buf : c_bot) + (size_t)(uint32_t)(ml1 & 0x7fffffff) * DDIM + colb);
            pf_l2(((mr0 < 0) ? c_buf : c_bot) + (size_t)(uint32_t)(mr0 & 0x7fffffff) * DDIM + colb);
            pf_l2(((mr1 < 0) ? c_buf : c_bot) + (size_t)(uint32_t)(mr1 & 0x7fffffff) * DDIM + colb);
        }
    }

    // ---- pass 1: f_l & f_r together ----
    run_pass<2, 8, 2>(w1, w2, smem, warpB_s, warpB_c, lane, acc, phase);
    #pragma unroll
    for (int mt = 0; mt < 4; mt++) {
        int r0 = mt * 16 + g;
        int ml0 = g_rowmap_l[mbase + r0], ml1 = g_rowmap_l[mbase + r0 + 8];
        int mr0 = g_rowmap_r[mbase + r0], mr1 = g_rowmap_r[mbase + r0 + 8];
        const float* cl0 = ((ml0 < 0) ? c_buf : c_bot) + (size_t)(uint32_t)(ml0 & 0x7fffffff) * DDIM;
        const float* cl1 = ((ml1 < 0) ? c_buf : c_bot) + (size_t)(uint32_t)(ml1 & 0x7fffffff) * DDIM;
        const float* cr0 = ((mr0 < 0) ? c_buf : c_bot) + (size_t)(uint32_t)(mr0 & 0x7fffffff) * DDIM;
        const float* cr1 = ((mr1 < 0) ? c_buf : c_bot) + (size_t)(uint32_t)(mr1 & 0x7fffffff) * DDIM;
        #pragma unroll
        for (int ntl = 0; ntl < 2; ntl++) {
            int colg = wq * 16 + ntl * 8 + tig * 2;
            float2 bl = *(const float2*)(bias + 384 + colg);   // f_l
            float2 br = *(const float2*)(bias + 512 + colg);   // f_r
            float2 vl0 = *(const float2*)(cl0 + colg);
            float2 vl1 = *(const float2*)(cl1 + colg);
            float2 vr0 = *(const float2*)(cr0 + colg);
            float2 vr1 = *(const float2*)(cr1 + colg);
            creg[mt][ntl][0] = fmaf(sigf(acc[0][mt][ntl][0] + bl.x), vl0.x, creg[mt][ntl][0]);
            creg[mt][ntl][1] = fmaf(sigf(acc[0][mt][ntl][1] + bl.y), vl0.y, creg[mt][ntl][1]);
            creg[mt][ntl][2] = fmaf(sigf(acc[0][mt][ntl][2] + bl.x), vl1.x, creg[mt][ntl][2]);
            creg[mt][ntl][3] = fmaf(sigf(acc[0][mt][ntl][3] + bl.y), vl1.y, creg[mt][ntl][3]);
            creg[mt][ntl][0] = fmaf(sigf(acc[1][mt][ntl][0] + br.x), vr0.x, creg[mt][ntl][0]);
            creg[mt][ntl][1] = fmaf(sigf(acc[1][mt][ntl][1] + br.y), vr0.y, creg[mt][ntl][1]);
            creg[mt][ntl][2] = fmaf(sigf(acc[1][mt][ntl][2] + br.x), vr1.x, creg[mt][ntl][2]);
            creg[mt][ntl][3] = fmaf(sigf(acc[1][mt][ntl][3] + br.y), vr1.y, creg[mt][ntl][3]);
        }
    }

    // ---- pass 2: o -> finalize h, c ----
    run_pass<1, 4, 4>(w2, nullptr, smem, warpB_s, warpB_c, lane, acc, phase);
    #pragma unroll
    for (int mt = 0; mt < 4; mt++) {
        size_t m0 = (size_t)(mbase + mt * 16 + g);
        size_t m1 = m0 + 8;
        #pragma unroll
        for (int ntl = 0; ntl < 2; ntl++) {
            int colg = wq * 16 + ntl * 8 + tig * 2;
            float2 bo = *(const float2*)(bias + 128 + colg);   // o: cols 128..255
            float2 h0, h1, c0, c1;
            c0.x = creg[mt][ntl][0]; h0.x = sigf(acc[0][mt][ntl][0] + bo.x) * tanhf_(c0.x);
            c0.y = creg[mt][ntl][1]; h0.y = sigf(acc[0][mt][ntl][1] + bo.y) * tanhf_(c0.y);
            c1.x = creg[mt][ntl][2]; h1.x = sigf(acc[0][mt][ntl][2] + bo.x) * tanhf_(c1.x);
            c1.y = creg[mt][ntl][3]; h1.y = sigf(acc[0][mt][ntl][3] + bo.y) * tanhf_(c1.y);
            *(float2*)(out + m0 * DDIM + colg) = h0;
            *(float2*)(out + m1 * DDIM + colg) = h1;
            *(float2*)(out + (size_t)MROWS * DDIM + m0 * DDIM + colg) = c0;
            *(float2*)(out + (size_t)MROWS * DDIM + m1 * DDIM + colg) = c1;
        }
    }
}

// ---------------- launch ----------------
extern "C" void kernel_launch(void* const* d_in, const int* in_sizes, int n_in,
                              void* d_out, int out_size) {
    const float* h_bot = (const float*)d_in[0];
    const float* c_bot = (const float*)d_in[1];
    const float* h_buf = (const float*)d_in[2];
    const float* c_buf = (const float*)d_in[3];
    const float* W     = (const float*)d_in[4];
    const float* b     = (const float*)d_in[5];
    const int* bf0 = (const int*)d_in[6];
    const int* bt0 = (const int*)d_in[7];
    const int* pf0 = (const int*)d_in[8];
    const int* pt0 = (const int*)d_in[9];
    const int* bf1 = (const int*)d_in[10];
    const int* bt1 = (const int*)d_in[11];
    const int* pf1 = (const int*)d_in[12];
    const int* pt1 = (const int*)d_in[13];
    float* out = (float*)d_out;

    cudaFuncSetAttribute(treelstm_main, cudaFuncAttributeMaxDynamicSharedMemorySize, SMEM_TOTAL);

    prep_all<<<640, 256>>>(W, bf0, bt0, pf0, pt0, bf1, bt1, pf1, pt1);
    treelstm_main<<<MROWS / 64, 256, SMEM_TOTAL>>>(h_bot, c_bot, h_buf, c_buf, b, out);
}